// round 1
// baseline (speedup 1.0000x reference)
#include <cuda_runtime.h>
#include <math.h>

// ---------------- scratch (device globals; no allocations allowed) ----------
__device__ float g_xp   [33554432];   // [B,16,1024,512]  x patch-split, channel-last
__device__ float g_xpt  [33554432];   // [B,16,512,1024]  x patch-split, pixel-last
__device__ float g_cam  [33554432];   // [B,16,512,1024]  cam^T, then pixel_conf in-place
__device__ float g_aff  [33554432];   // [B,16,1024,512]
__device__ float g_local[16777216];   // [B,16,512,512]
__device__ float g_g    [16777216];   // relu(gcn1 mix + local)
__device__ float g_lf   [16777216];   // local_feats
__device__ float g_query[16777216];   // [B,16,1024,256]
__device__ float g_oattn[16777216];   // [B,16,1024,256]
__device__ float g_key  [ 8388608];   // [B,16,512,256]
__device__ float g_glob [ 1048576];   // [B,512,512]
__device__ float g_valT [  524288];   // [B,256,512]  value transposed
__device__ float g_bconf[   32768];   // [B,16,512]
__device__ float g_bnS  [     512];
__device__ float g_bnT  [     512];

// ---------------- small helpers --------------------------------------------
__device__ __forceinline__ float warpRedSum(float v){
#pragma unroll
    for (int o = 16; o; o >>= 1) v += __shfl_xor_sync(0xffffffffu, v, o);
    return v;
}
__device__ __forceinline__ float warpRedMax(float v){
#pragma unroll
    for (int o = 16; o; o >>= 1) v = fmaxf(v, __shfl_xor_sync(0xffffffffu, v, o));
    return v;
}

// ---------------- BN constant prep ------------------------------------------
__global__ void prep_bn(const float* __restrict__ gam, const float* __restrict__ bet,
                        const float* __restrict__ mean, const float* __restrict__ var,
                        float* __restrict__ S, float* __restrict__ T)
{
    int i = threadIdx.x;
    if (i < 512) {
        float inv = rsqrtf(var[i] + 1e-5f);
        float s = gam[i] * inv;
        S[i] = s;
        T[i] = bet[i] - mean[i] * s;
    }
}

// ---------------- patch-split transposes: x -> x_p ([p,c]) and x_pT ([c,p]) --
// grid (C/32=16, rH=32, B*bins=64), block (32,8)
__global__ void make_xp(const float* __restrict__ x,
                        float* __restrict__ xp, float* __restrict__ xpt)
{
    __shared__ float t[32][33];
    const int ct = blockIdx.x * 32;
    const int rh = blockIdx.y;
    const int z  = blockIdx.z;            // b*16 + nbin
    const int b  = z >> 4, n = z & 15;
    const int h  = (n >> 2) * 32 + rh;
    const int wb = (n & 3) * 32;
    const int tx = threadIdx.x, ty = threadIdx.y;

    const float* xb = x + ((((long long)b * 512 + ct) * 128 + h) * 128 + wb);
#pragma unroll
    for (int i = 0; i < 4; i++) {
        int cc = ty + 8 * i;
        t[cc][tx] = xb[(long long)cc * 16384 + tx];
    }
    __syncthreads();
    // xp[z][p = rh*32+rw][ct+tx]
    float* xpb = xp + (((long long)z * 1024 + rh * 32) * 512) + ct;
#pragma unroll
    for (int i = 0; i < 4; i++) {
        int rw = ty + 8 * i;
        xpb[(long long)rw * 512 + tx] = t[tx][rw];
    }
    // xpt[z][ct+cc][p = rh*32+tx]
    float* xptb = xpt + (((long long)z * 512 + ct) * 1024) + rh * 32;
#pragma unroll
    for (int i = 0; i < 4; i++) {
        int cc = ty + 8 * i;
        xptb[(long long)cc * 1024 + tx] = t[cc][tx];
    }
}

// ---------------- row softmax (in place), optional sigmoid(mean) side output -
// blockDim.x == rowlen/4 (one float4 per thread)
template<bool HASCONF>
__global__ void softmax_rows(float* __restrict__ data, float* __restrict__ conf, int rowlen)
{
    const int tid = threadIdx.x;
    const long long r = blockIdx.x;
    float4* row = (float4*)(data + r * (long long)rowlen);
    float4 v = row[tid];

    float lmax = fmaxf(fmaxf(v.x, v.y), fmaxf(v.z, v.w));
    float lsum = v.x + v.y + v.z + v.w;

    __shared__ float sm[32], ss[32];
    const int lane = tid & 31, wid = tid >> 5, nw = blockDim.x >> 5;
    float wmax = warpRedMax(lmax), wsum = warpRedSum(lsum);
    if (lane == 0) { sm[wid] = wmax; ss[wid] = wsum; }
    __syncthreads();
    if (tid < 32) {
        float a  = (tid < nw) ? sm[tid] : -3.402823466e38f;
        float b2 = (tid < nw) ? ss[tid] : 0.f;
        a  = warpRedMax(a);
        b2 = warpRedSum(b2);
        if (tid == 0) { sm[0] = a; ss[0] = b2; }
    }
    __syncthreads();
    const float rmax = sm[0];
    if (HASCONF && tid == 0)
        conf[r] = 1.f / (1.f + expf(-ss[0] / (float)rowlen));
    __syncthreads();   // protect ss before reuse

    float4 e;
    e.x = expf(v.x - rmax); e.y = expf(v.y - rmax);
    e.z = expf(v.z - rmax); e.w = expf(v.w - rmax);
    float les = e.x + e.y + e.z + e.w;
    float ws = warpRedSum(les);
    if (lane == 0) ss[wid] = ws;
    __syncthreads();
    if (tid < 32) {
        float b2 = (tid < nw) ? ss[tid] : 0.f;
        b2 = warpRedSum(b2);
        if (tid == 0) ss[0] = b2;
    }
    __syncthreads();
    const float inv = 1.f / ss[0];
    e.x *= inv; e.y *= inv; e.z *= inv; e.w *= inv;
    row[tid] = e;
}

// ---------------- GCN 16x16 bin mix + residual relu -------------------------
// out[b,n,j] = relu(local[b,n,j] + sum_m w1[n,m]*local[b,m,j]),  j in [0,512*512)
__global__ void gcn_mix(const float* __restrict__ local, const float* __restrict__ w1,
                        float* __restrict__ g)
{
    __shared__ float w[256];
    if (threadIdx.x < 256) w[threadIdx.x] = w1[threadIdx.x];
    __syncthreads();
    long long j = (long long)blockIdx.x * blockDim.x + threadIdx.x;  // over 4*262144
    const int b = (int)(j >> 18);
    const long long jj = j & 262143;
    const float* base = local + ((long long)b << 22) + jj;
    float v[16];
#pragma unroll
    for (int m = 0; m < 16; m++) v[m] = base[(long long)m << 18];
    float* ob = g + ((long long)b << 22) + jj;
#pragma unroll
    for (int n = 0; n < 16; n++) {
        float s = v[n];
#pragma unroll
        for (int m = 0; m < 16; m++) s = fmaf(w[n * 16 + m], v[m], s);
        ob[(long long)n << 18] = fmaxf(s, 0.f);
    }
}

// ---------------- fuse: glob[b,j] = relu(b_fuse + sum_m w_fuse[m]*lf[b,m,j]) -
__global__ void fuse_glob(const float* __restrict__ lf, const float* __restrict__ wf,
                          const float* __restrict__ bf, float* __restrict__ glob)
{
    __shared__ float w[16];
    __shared__ float b0;
    if (threadIdx.x < 16) w[threadIdx.x] = wf[threadIdx.x];
    if (threadIdx.x == 16) b0 = bf[0];
    __syncthreads();
    long long j = (long long)blockIdx.x * blockDim.x + threadIdx.x;
    const int b = (int)(j >> 18);
    const long long jj = j & 262143;
    const float* base = lf + ((long long)b << 22) + jj;
    float s = b0;
#pragma unroll
    for (int m = 0; m < 16; m++) s = fmaf(w[m], base[(long long)m << 18], s);
    glob[((long long)b << 18) + jj] = fmaxf(s, 0.f);
}

// ---------------- generic TN SGEMM: C[m,n] = sum_kd A[m,kd]*B[n,kd] ----------
// 128x128x8 tile, 256 threads, 8x8 microtile. M,N multiples of 128, Kd of 8.
// epi==0: store C (optional bias per-row/col, optional per-row scale)
// epi==2: fused BN+ReLU+residual+patch_recover into outp ([B,512,128,128])
__global__ __launch_bounds__(256) void gemm_tn(
    const float* __restrict__ Ab, const float* __restrict__ Bb, float* __restrict__ Cb,
    int N, int Kd,
    long long sA, long long sB, long long sC, int zdivB,
    const float* __restrict__ bias, int biasMode,
    const float* __restrict__ rowscale, long long sScale,
    int epi,
    const float* __restrict__ resid, const float* __restrict__ bnS,
    const float* __restrict__ bnT, float* __restrict__ outp)
{
    const int z = blockIdx.z;
    const float* A = Ab + (long long)z * sA;
    const float* B = Bb + (long long)(z / zdivB) * sB;

    __shared__ float As[8][128];
    __shared__ float Bs[8][128];

    const int tid  = threadIdx.x;
    const int m0   = blockIdx.y * 128;
    const int n0   = blockIdx.x * 128;
    const int lrow = tid >> 1;
    const int lcol = (tid & 1) * 4;

    const float* Aptr = A + (long long)(m0 + lrow) * Kd + lcol;
    const float* Bptr = B + (long long)(n0 + lrow) * Kd + lcol;

    float acc[8][8];
#pragma unroll
    for (int i = 0; i < 8; i++)
#pragma unroll
        for (int j = 0; j < 8; j++) acc[i][j] = 0.f;

    const int tm = (tid >> 4) * 8;
    const int tn = (tid & 15) * 8;

    float4 av = *(const float4*)Aptr;
    float4 bv = *(const float4*)Bptr;

    for (int k0 = 0; k0 < Kd; k0 += 8) {
        As[lcol + 0][lrow] = av.x; As[lcol + 1][lrow] = av.y;
        As[lcol + 2][lrow] = av.z; As[lcol + 3][lrow] = av.w;
        Bs[lcol + 0][lrow] = bv.x; Bs[lcol + 1][lrow] = bv.y;
        Bs[lcol + 2][lrow] = bv.z; Bs[lcol + 3][lrow] = bv.w;
        __syncthreads();
        if (k0 + 8 < Kd) {                    // prefetch next tile
            Aptr += 8; Bptr += 8;
            av = *(const float4*)Aptr;
            bv = *(const float4*)Bptr;
        }
#pragma unroll
        for (int k = 0; k < 8; k++) {
            float a[8], b[8];
            *(float4*)(a)     = *(const float4*)&As[k][tm];
            *(float4*)(a + 4) = *(const float4*)&As[k][tm + 4];
            *(float4*)(b)     = *(const float4*)&Bs[k][tn];
            *(float4*)(b + 4) = *(const float4*)&Bs[k][tn + 4];
#pragma unroll
            for (int i = 0; i < 8; i++)
#pragma unroll
                for (int j = 0; j < 8; j++)
                    acc[i][j] = fmaf(a[i], b[j], acc[i][j]);
        }
        __syncthreads();
    }

    if (biasMode == 1) {
#pragma unroll
        for (int i = 0; i < 8; i++) {
            float bb = bias[m0 + tm + i];
#pragma unroll
            for (int j = 0; j < 8; j++) acc[i][j] += bb;
        }
    } else if (biasMode == 2) {
        float bb[8];
#pragma unroll
        for (int j = 0; j < 8; j++) bb[j] = bias[n0 + tn + j];
#pragma unroll
        for (int i = 0; i < 8; i++)
#pragma unroll
            for (int j = 0; j < 8; j++) acc[i][j] += bb[j];
    }
    if (rowscale) {
        const float* rs = rowscale + (long long)z * sScale;
#pragma unroll
        for (int i = 0; i < 8; i++) {
            float f = rs[m0 + tm + i];
#pragma unroll
            for (int j = 0; j < 8; j++) acc[i][j] *= f;
        }
    }

    if (epi == 0) {
        float* C = Cb + (long long)z * sC;
#pragma unroll
        for (int i = 0; i < 8; i++) {
            float* cp = C + (long long)(m0 + tm + i) * N + n0 + tn;
            *(float4*)cp       = make_float4(acc[i][0], acc[i][1], acc[i][2], acc[i][3]);
            *(float4*)(cp + 4) = make_float4(acc[i][4], acc[i][5], acc[i][6], acc[i][7]);
        }
    } else {
        // final: m=channel co, n=p within bin z; BN + relu + residual, patch-recover
        const int b = z >> 4, nbin = z & 15;
        const int hb = (nbin >> 2) * 32, wb = (nbin & 3) * 32;
#pragma unroll
        for (int i = 0; i < 8; i++) {
            const int co = m0 + tm + i;
            const float s = bnS[co], t = bnT[co];
            const int p0 = n0 + tn;                       // multiple of 8 -> same h row
            const int h = hb + (p0 >> 5);
            const int w0 = wb + (p0 & 31);
            const long long oi = (((long long)(b * 512 + co) * 128) + h) * 128 + w0;
#pragma unroll
            for (int j = 0; j < 8; j++) {
                float v = fmaf(acc[i][j], s, t);
                v = fmaxf(v, 0.f);
                outp[oi + j] = resid[oi + j] + v;
            }
        }
    }
}

// ---------------- host side --------------------------------------------------
static void gemm(const float* A, const float* B, float* C, int M, int N, int Kd,
                 long long sA, long long sB, long long sC, int Z, int zdivB = 1,
                 const float* bias = nullptr, int biasMode = 0,
                 const float* rowscale = nullptr, long long sScale = 0,
                 int epi = 0, const float* resid = nullptr,
                 const float* bnS = nullptr, const float* bnT = nullptr,
                 float* outp = nullptr)
{
    dim3 grid(N / 128, M / 128, Z), block(256);
    gemm_tn<<<grid, block>>>(A, B, C, N, Kd, sA, sB, sC, zdivB,
                             bias, biasMode, rowscale, sScale,
                             epi, resid, bnS, bnT, outp);
}

extern "C" void kernel_launch(void* const* d_in, const int* in_sizes, int n_in,
                              void* d_out, int out_size)
{
    const float* x      = (const float*)d_in[0];
    const float* w_cam  = (const float*)d_in[1];
    const float* b_cam  = (const float*)d_in[2];
    const float* w_gcn1 = (const float*)d_in[3];
    const float* w_gcn2 = (const float*)d_in[4];
    const float* w_fuse = (const float*)d_in[5];
    const float* b_fuse = (const float*)d_in[6];
    const float* w_q    = (const float*)d_in[7];
    const float* b_q    = (const float*)d_in[8];
    const float* w_k    = (const float*)d_in[9];
    const float* b_k    = (const float*)d_in[10];
    const float* w_v    = (const float*)d_in[11];
    const float* b_v    = (const float*)d_in[12];
    const float* w_out  = (const float*)d_in[13];
    const float* bn_g   = (const float*)d_in[14];
    const float* bn_b   = (const float*)d_in[15];
    const float* bn_m   = (const float*)d_in[16];
    const float* bn_v   = (const float*)d_in[17];
    float* out = (float*)d_out;

    float *xp, *xpt, *cam, *aff, *loc, *gg, *lf, *qry, *oat, *key, *glob, *valT, *bconf, *bnS, *bnT;
    cudaGetSymbolAddress((void**)&xp,    g_xp);
    cudaGetSymbolAddress((void**)&xpt,   g_xpt);
    cudaGetSymbolAddress((void**)&cam,   g_cam);
    cudaGetSymbolAddress((void**)&aff,   g_aff);
    cudaGetSymbolAddress((void**)&loc,   g_local);
    cudaGetSymbolAddress((void**)&gg,    g_g);
    cudaGetSymbolAddress((void**)&lf,    g_lf);
    cudaGetSymbolAddress((void**)&qry,   g_query);
    cudaGetSymbolAddress((void**)&oat,   g_oattn);
    cudaGetSymbolAddress((void**)&key,   g_key);
    cudaGetSymbolAddress((void**)&glob,  g_glob);
    cudaGetSymbolAddress((void**)&valT,  g_valT);
    cudaGetSymbolAddress((void**)&bconf, g_bconf);
    cudaGetSymbolAddress((void**)&bnS,   g_bnS);
    cudaGetSymbolAddress((void**)&bnT,   g_bnT);

    // BN constants
    prep_bn<<<1, 512>>>(bn_g, bn_b, bn_m, bn_v, bnS, bnT);

    // patch-split transposes
    make_xp<<<dim3(16, 32, 64), dim3(32, 8)>>>(x, xp, xpt);

    // cam^T[b,n,k,p] = w_cam @ x_p^T (+b_cam per row k)
    gemm(w_cam, xp, cam, 512, 1024, 512, 0, 524288, 524288, 64, 1, b_cam, 1);

    // pixel softmax over p (rows of 1024) + bin_conf = sigmoid(row mean)
    softmax_rows<true><<<32768, 256>>>(cam, bconf, 1024);

    // local[b,n,k,c] = (conf^T @ x_p) * bin_conf[k]
    gemm(cam, xpt, loc, 512, 512, 1024, 524288, 524288, 262144, 64, 1,
         nullptr, 0, bconf, 512);

    // GCN bin mix + residual relu
    gcn_mix<<<4096, 256>>>(loc, w_gcn1, gg);

    // local_feats = g @ w_gcn2^T   (rows flattened: 32768 x 512)
    gemm(gg, w_gcn2, lf, 32768, 512, 512, 0, 0, 0, 1);

    // glob = relu(fuse over bins + b_fuse)
    fuse_glob<<<4096, 256>>>(lf, w_fuse, b_fuse, glob);

    // query / key / value^T
    gemm(xp, w_q, qry, 65536, 256, 512, 0, 0, 0, 1, 1, b_q, 2);
    gemm(lf, w_k, key, 32768, 256, 512, 0, 0, 0, 1, 1, b_k, 2);
    gemm(w_v, glob, valT, 256, 512, 512, 0, 262144, 131072, 4, 1, b_v, 1);

    // aff = query @ key^T per (b,bin); softmax over k
    gemm(qry, key, aff, 1024, 512, 256, 262144, 131072, 524288, 64);
    softmax_rows<false><<<65536, 128>>>(aff, nullptr, 512);

    // out_attn = aff @ value  (value shared across bins: zdivB=16)
    gemm(aff, valT, oat, 1024, 256, 512, 524288, 131072, 262144, 64, 16);

    // final 1x1 conv + BN + relu + residual, patch-recover fused epilogue
    gemm(w_out, oat, nullptr, 512, 1024, 256, 0, 262144, 0, 64, 1,
         nullptr, 0, nullptr, 0, 2, x, bnS, bnT, out);
}

// round 2
// speedup vs baseline: 1.6367x; 1.6367x over previous
#include <cuda_runtime.h>
#include <math.h>

// ---------------- scratch (device globals; no allocations allowed) ----------
__device__ float g_xp   [33554432];   // [B,16,1024,512]  x patch-split, channel-last
__device__ float g_xpt  [33554432];   // [B,16,512,1024]  x patch-split, pixel-last
__device__ float g_cam  [33554432];   // [B,16,512,1024]  cam^T, then pixel_conf in-place
__device__ float g_aff  [33554432];   // [B,16,1024,512]
__device__ float g_local[16777216];   // [B,16,512,512]
__device__ float g_g    [16777216];   // relu(gcn1 mix + local)
__device__ float g_lf   [16777216];   // local_feats
__device__ float g_query[16777216];   // [B,16,1024,256]
__device__ float g_oattn[16777216];   // [B,16,1024,256]
__device__ float g_key  [ 8388608];   // [B,16,512,256]
__device__ float g_glob [ 1048576];   // [B,512,512]
__device__ float g_valT [  524288];   // [B,256,512]  value transposed
__device__ float g_bconf[   32768];   // [B,16,512]
__device__ float g_bnS  [     512];
__device__ float g_bnT  [     512];

// ---------------- small helpers --------------------------------------------
__device__ __forceinline__ float warpRedSum(float v){
#pragma unroll
    for (int o = 16; o; o >>= 1) v += __shfl_xor_sync(0xffffffffu, v, o);
    return v;
}
__device__ __forceinline__ float warpRedMax(float v){
#pragma unroll
    for (int o = 16; o; o >>= 1) v = fmaxf(v, __shfl_xor_sync(0xffffffffu, v, o));
    return v;
}
__device__ __forceinline__ unsigned f2tf32(float f){
    unsigned u;
    asm("cvt.rna.tf32.f32 %0, %1;" : "=r"(u) : "f"(f));
    return u;
}
__device__ __forceinline__ void mma_tf32(float* d, const unsigned* a, const unsigned* b){
    asm volatile(
        "mma.sync.aligned.m16n8k8.row.col.f32.tf32.tf32.f32 "
        "{%0,%1,%2,%3}, {%4,%5,%6,%7}, {%8,%9}, {%0,%1,%2,%3};"
        : "+f"(d[0]), "+f"(d[1]), "+f"(d[2]), "+f"(d[3])
        : "r"(a[0]), "r"(a[1]), "r"(a[2]), "r"(a[3]), "r"(b[0]), "r"(b[1]));
}

// ---------------- BN constant prep ------------------------------------------
__global__ void prep_bn(const float* __restrict__ gam, const float* __restrict__ bet,
                        const float* __restrict__ mean, const float* __restrict__ var,
                        float* __restrict__ S, float* __restrict__ T)
{
    int i = threadIdx.x;
    if (i < 512) {
        float inv = rsqrtf(var[i] + 1e-5f);
        float s = gam[i] * inv;
        S[i] = s;
        T[i] = bet[i] - mean[i] * s;
    }
}

// ---------------- patch-split transposes: x -> x_p ([p,c]) and x_pT ([c,p]) --
__global__ void make_xp(const float* __restrict__ x,
                        float* __restrict__ xp, float* __restrict__ xpt)
{
    __shared__ float t[32][33];
    const int ct = blockIdx.x * 32;
    const int rh = blockIdx.y;
    const int z  = blockIdx.z;            // b*16 + nbin
    const int b  = z >> 4, n = z & 15;
    const int h  = (n >> 2) * 32 + rh;
    const int wb = (n & 3) * 32;
    const int tx = threadIdx.x, ty = threadIdx.y;

    const float* xb = x + ((((long long)b * 512 + ct) * 128 + h) * 128 + wb);
#pragma unroll
    for (int i = 0; i < 4; i++) {
        int cc = ty + 8 * i;
        t[cc][tx] = xb[(long long)cc * 16384 + tx];
    }
    __syncthreads();
    float* xpb = xp + (((long long)z * 1024 + rh * 32) * 512) + ct;
#pragma unroll
    for (int i = 0; i < 4; i++) {
        int rw = ty + 8 * i;
        xpb[(long long)rw * 512 + tx] = t[tx][rw];
    }
    float* xptb = xpt + (((long long)z * 512 + ct) * 1024) + rh * 32;
#pragma unroll
    for (int i = 0; i < 4; i++) {
        int cc = ty + 8 * i;
        xptb[(long long)cc * 1024 + tx] = t[cc][tx];
    }
}

// ---------------- row softmax (in place), optional sigmoid(mean) side output -
template<bool HASCONF>
__global__ void softmax_rows(float* __restrict__ data, float* __restrict__ conf, int rowlen)
{
    const int tid = threadIdx.x;
    const long long r = blockIdx.x;
    float4* row = (float4*)(data + r * (long long)rowlen);
    float4 v = row[tid];

    float lmax = fmaxf(fmaxf(v.x, v.y), fmaxf(v.z, v.w));
    float lsum = v.x + v.y + v.z + v.w;

    __shared__ float sm[32], ss[32];
    const int lane = tid & 31, wid = tid >> 5, nw = blockDim.x >> 5;
    float wmax = warpRedMax(lmax), wsum = warpRedSum(lsum);
    if (lane == 0) { sm[wid] = wmax; ss[wid] = wsum; }
    __syncthreads();
    if (tid < 32) {
        float a  = (tid < nw) ? sm[tid] : -3.402823466e38f;
        float b2 = (tid < nw) ? ss[tid] : 0.f;
        a  = warpRedMax(a);
        b2 = warpRedSum(b2);
        if (tid == 0) { sm[0] = a; ss[0] = b2; }
    }
    __syncthreads();
    const float rmax = sm[0];
    if (HASCONF && tid == 0)
        conf[r] = 1.f / (1.f + expf(-ss[0] / (float)rowlen));
    __syncthreads();

    float4 e;
    e.x = expf(v.x - rmax); e.y = expf(v.y - rmax);
    e.z = expf(v.z - rmax); e.w = expf(v.w - rmax);
    float les = e.x + e.y + e.z + e.w;
    float ws = warpRedSum(les);
    if (lane == 0) ss[wid] = ws;
    __syncthreads();
    if (tid < 32) {
        float b2 = (tid < nw) ? ss[tid] : 0.f;
        b2 = warpRedSum(b2);
        if (tid == 0) ss[0] = b2;
    }
    __syncthreads();
    const float inv = 1.f / ss[0];
    e.x *= inv; e.y *= inv; e.z *= inv; e.w *= inv;
    row[tid] = e;
}

// ---------------- GCN 16x16 bin mix + residual relu -------------------------
__global__ void gcn_mix(const float* __restrict__ local, const float* __restrict__ w1,
                        float* __restrict__ g)
{
    __shared__ float w[256];
    if (threadIdx.x < 256) w[threadIdx.x] = w1[threadIdx.x];
    __syncthreads();
    long long j = (long long)blockIdx.x * blockDim.x + threadIdx.x;
    const int b = (int)(j >> 18);
    const long long jj = j & 262143;
    const float* base = local + ((long long)b << 22) + jj;
    float v[16];
#pragma unroll
    for (int m = 0; m < 16; m++) v[m] = base[(long long)m << 18];
    float* ob = g + ((long long)b << 22) + jj;
#pragma unroll
    for (int n = 0; n < 16; n++) {
        float s = v[n];
#pragma unroll
        for (int m = 0; m < 16; m++) s = fmaf(w[n * 16 + m], v[m], s);
        ob[(long long)n << 18] = fmaxf(s, 0.f);
    }
}

// ---------------- fuse: glob[b,j] = relu(b_fuse + sum_m w_fuse[m]*lf[b,m,j]) -
__global__ void fuse_glob(const float* __restrict__ lf, const float* __restrict__ wf,
                          const float* __restrict__ bf, float* __restrict__ glob)
{
    __shared__ float w[16];
    __shared__ float b0;
    if (threadIdx.x < 16) w[threadIdx.x] = wf[threadIdx.x];
    if (threadIdx.x == 16) b0 = bf[0];
    __syncthreads();
    long long j = (long long)blockIdx.x * blockDim.x + threadIdx.x;
    const int b = (int)(j >> 18);
    const long long jj = j & 262143;
    const float* base = lf + ((long long)b << 22) + jj;
    float s = b0;
#pragma unroll
    for (int m = 0; m < 16; m++) s = fmaf(w[m], base[(long long)m << 18], s);
    glob[((long long)b << 18) + jj] = fmaxf(s, 0.f);
}

// ---------------- TN GEMM via mma.sync tf32 ----------------------------------
// C[m,n] = sum_kd A[m,kd]*B[n,kd]. CTA tile 128x128, k-tile 16 double-buffered.
// 8 warps, warp tile 32(M) x 64(N), mma m16n8k8.tf32, fp32 accumulate.
// M,N multiples of 128; Kd multiple of 16.
__global__ __launch_bounds__(256) void gemm_tn_tc(
    const float* __restrict__ Ab, const float* __restrict__ Bb, float* __restrict__ Cb,
    int N, int Kd,
    long long sA, long long sB, long long sC, int zdivB,
    const float* __restrict__ bias, int biasMode,
    const float* __restrict__ rowscale, long long sScale,
    int epi,
    const float* __restrict__ resid, const float* __restrict__ bnS,
    const float* __restrict__ bnT, float* __restrict__ outp)
{
    __shared__ unsigned As[2][16][132];
    __shared__ unsigned Bs[2][16][132];

    const int z = blockIdx.z;
    const float* A = Ab + (long long)z * sA;
    const float* B = Bb + (long long)(z / zdivB) * sB;

    const int tid  = threadIdx.x;
    const int m0   = blockIdx.y * 128;
    const int n0   = blockIdx.x * 128;

    const int lane = tid & 31;
    const int warp = tid >> 5;
    const int gq   = lane >> 2;      // 0..7
    const int tq   = lane & 3;       // 0..3
    const int m0w  = (warp >> 1) * 32;
    const int n0w  = (warp & 1) * 64;

    // global->smem assignment: row r = tid>>1 (0..127), k-cols kc..kc+7
    const int r  = tid >> 1;
    const int kc = (tid & 1) * 8;
    const float* Ag = A + (long long)(m0 + r) * Kd + kc;
    const float* Bg = B + (long long)(n0 + r) * Kd + kc;

    float acc[2][8][4];
#pragma unroll
    for (int i = 0; i < 2; i++)
#pragma unroll
        for (int j = 0; j < 8; j++)
#pragma unroll
            for (int q = 0; q < 4; q++) acc[i][j][q] = 0.f;

    float4 pa0 = *(const float4*)Ag;
    float4 pa1 = *(const float4*)(Ag + 4);
    float4 pb0 = *(const float4*)Bg;
    float4 pb1 = *(const float4*)(Bg + 4);

    // store tile 0
    {
        unsigned (*Sa)[132] = As[0];
        unsigned (*Sb)[132] = Bs[0];
        Sa[kc + 0][r] = f2tf32(pa0.x); Sa[kc + 1][r] = f2tf32(pa0.y);
        Sa[kc + 2][r] = f2tf32(pa0.z); Sa[kc + 3][r] = f2tf32(pa0.w);
        Sa[kc + 4][r] = f2tf32(pa1.x); Sa[kc + 5][r] = f2tf32(pa1.y);
        Sa[kc + 6][r] = f2tf32(pa1.z); Sa[kc + 7][r] = f2tf32(pa1.w);
        Sb[kc + 0][r] = f2tf32(pb0.x); Sb[kc + 1][r] = f2tf32(pb0.y);
        Sb[kc + 2][r] = f2tf32(pb0.z); Sb[kc + 3][r] = f2tf32(pb0.w);
        Sb[kc + 4][r] = f2tf32(pb1.x); Sb[kc + 5][r] = f2tf32(pb1.y);
        Sb[kc + 6][r] = f2tf32(pb1.z); Sb[kc + 7][r] = f2tf32(pb1.w);
    }
    __syncthreads();

    int s = 0;
    for (int k0 = 0; ; ) {
        const bool last = (k0 + 16 >= Kd);
        if (!last) {
            Ag += 16; Bg += 16;
            pa0 = *(const float4*)Ag; pa1 = *(const float4*)(Ag + 4);
            pb0 = *(const float4*)Bg; pb1 = *(const float4*)(Bg + 4);
        }
        // compute two k8 steps from buffer s
#pragma unroll
        for (int kk = 0; kk < 16; kk += 8) {
            unsigned af[2][4], bf[8][2];
#pragma unroll
            for (int mt = 0; mt < 2; mt++) {
                const int mr = m0w + mt * 16 + gq;
                af[mt][0] = As[s][kk + tq    ][mr    ];
                af[mt][1] = As[s][kk + tq    ][mr + 8];
                af[mt][2] = As[s][kk + tq + 4][mr    ];
                af[mt][3] = As[s][kk + tq + 4][mr + 8];
            }
#pragma unroll
            for (int nt = 0; nt < 8; nt++) {
                const int nc = n0w + nt * 8 + gq;
                bf[nt][0] = Bs[s][kk + tq    ][nc];
                bf[nt][1] = Bs[s][kk + tq + 4][nc];
            }
#pragma unroll
            for (int mt = 0; mt < 2; mt++)
#pragma unroll
                for (int nt = 0; nt < 8; nt++)
                    mma_tf32(acc[mt][nt], af[mt], bf[nt]);
        }
        if (last) break;
        k0 += 16;
        {
            unsigned (*Sa)[132] = As[s ^ 1];
            unsigned (*Sb)[132] = Bs[s ^ 1];
            Sa[kc + 0][r] = f2tf32(pa0.x); Sa[kc + 1][r] = f2tf32(pa0.y);
            Sa[kc + 2][r] = f2tf32(pa0.z); Sa[kc + 3][r] = f2tf32(pa0.w);
            Sa[kc + 4][r] = f2tf32(pa1.x); Sa[kc + 5][r] = f2tf32(pa1.y);
            Sa[kc + 6][r] = f2tf32(pa1.z); Sa[kc + 7][r] = f2tf32(pa1.w);
            Sb[kc + 0][r] = f2tf32(pb0.x); Sb[kc + 1][r] = f2tf32(pb0.y);
            Sb[kc + 2][r] = f2tf32(pb0.z); Sb[kc + 3][r] = f2tf32(pb0.w);
            Sb[kc + 4][r] = f2tf32(pb1.x); Sb[kc + 5][r] = f2tf32(pb1.y);
            Sb[kc + 6][r] = f2tf32(pb1.z); Sb[kc + 7][r] = f2tf32(pb1.w);
        }
        __syncthreads();
        s ^= 1;
    }

    // ---- epilogue ----
    // element (mt, h, nt, q): row = m0+m0w+mt*16+gq+h*8 ; col = n0+n0w+nt*8+2*tq+q
    if (biasMode == 1) {
#pragma unroll
        for (int mt = 0; mt < 2; mt++)
#pragma unroll
            for (int h = 0; h < 2; h++) {
                const float bb = bias[m0 + m0w + mt * 16 + gq + h * 8];
#pragma unroll
                for (int nt = 0; nt < 8; nt++) {
                    acc[mt][nt][h * 2 + 0] += bb;
                    acc[mt][nt][h * 2 + 1] += bb;
                }
            }
    } else if (biasMode == 2) {
#pragma unroll
        for (int nt = 0; nt < 8; nt++) {
            const int c0 = n0 + n0w + nt * 8 + 2 * tq;
            const float b0v = bias[c0], b1v = bias[c0 + 1];
#pragma unroll
            for (int mt = 0; mt < 2; mt++) {
                acc[mt][nt][0] += b0v; acc[mt][nt][1] += b1v;
                acc[mt][nt][2] += b0v; acc[mt][nt][3] += b1v;
            }
        }
    }
    if (rowscale) {
        const float* rs = rowscale + (long long)z * sScale;
#pragma unroll
        for (int mt = 0; mt < 2; mt++)
#pragma unroll
            for (int h = 0; h < 2; h++) {
                const float f = rs[m0 + m0w + mt * 16 + gq + h * 8];
#pragma unroll
                for (int nt = 0; nt < 8; nt++) {
                    acc[mt][nt][h * 2 + 0] *= f;
                    acc[mt][nt][h * 2 + 1] *= f;
                }
            }
    }

    if (epi == 0) {
        float* C = Cb + (long long)z * sC;
#pragma unroll
        for (int mt = 0; mt < 2; mt++)
#pragma unroll
            for (int h = 0; h < 2; h++) {
                const int row = m0 + m0w + mt * 16 + gq + h * 8;
                float* cp = C + (long long)row * N + n0 + n0w + 2 * tq;
#pragma unroll
                for (int nt = 0; nt < 8; nt++)
                    *(float2*)(cp + nt * 8) =
                        make_float2(acc[mt][nt][h * 2 + 0], acc[mt][nt][h * 2 + 1]);
            }
    } else {
        // final conv: row=channel co, col=p within bin z. BN+relu+residual,
        // patch-recover into [B,512,128,128].
        const int b = z >> 4, nbin = z & 15;
        const int hb = (nbin >> 2) * 32, wb = (nbin & 3) * 32;
#pragma unroll
        for (int mt = 0; mt < 2; mt++)
#pragma unroll
            for (int h2 = 0; h2 < 2; h2++) {
                const int co = m0 + m0w + mt * 16 + gq + h2 * 8;
                const float sc = bnS[co], tt = bnT[co];
                const long long cbase = ((long long)(b * 512 + co) * 128);
#pragma unroll
                for (int nt = 0; nt < 8; nt++) {
                    const int p = n0 + n0w + nt * 8 + 2 * tq;   // even
                    const int hh = hb + (p >> 5);
                    const int ww = wb + (p & 31);
                    const long long oi = (cbase + hh) * 128 + ww;
                    float2 rv = *(const float2*)(resid + oi);
                    float v0 = fmaxf(fmaf(acc[mt][nt][h2 * 2 + 0], sc, tt), 0.f);
                    float v1 = fmaxf(fmaf(acc[mt][nt][h2 * 2 + 1], sc, tt), 0.f);
                    *(float2*)(outp + oi) = make_float2(rv.x + v0, rv.y + v1);
                }
            }
    }
}

// ---------------- host side --------------------------------------------------
static void gemm(const float* A, const float* B, float* C, int M, int N, int Kd,
                 long long sA, long long sB, long long sC, int Z, int zdivB = 1,
                 const float* bias = nullptr, int biasMode = 0,
                 const float* rowscale = nullptr, long long sScale = 0,
                 int epi = 0, const float* resid = nullptr,
                 const float* bnS = nullptr, const float* bnT = nullptr,
                 float* outp = nullptr)
{
    dim3 grid(N / 128, M / 128, Z), block(256);
    gemm_tn_tc<<<grid, block>>>(A, B, C, N, Kd, sA, sB, sC, zdivB,
                                bias, biasMode, rowscale, sScale,
                                epi, resid, bnS, bnT, outp);
}

extern "C" void kernel_launch(void* const* d_in, const int* in_sizes, int n_in,
                              void* d_out, int out_size)
{
    const float* x      = (const float*)d_in[0];
    const float* w_cam  = (const float*)d_in[1];
    const float* b_cam  = (const float*)d_in[2];
    const float* w_gcn1 = (const float*)d_in[3];
    const float* w_gcn2 = (const float*)d_in[4];
    const float* w_fuse = (const float*)d_in[5];
    const float* b_fuse = (const float*)d_in[6];
    const float* w_q    = (const float*)d_in[7];
    const float* b_q    = (const float*)d_in[8];
    const float* w_k    = (const float*)d_in[9];
    const float* b_k    = (const float*)d_in[10];
    const float* w_v    = (const float*)d_in[11];
    const float* b_v    = (const float*)d_in[12];
    const float* w_out  = (const float*)d_in[13];
    const float* bn_g   = (const float*)d_in[14];
    const float* bn_b   = (const float*)d_in[15];
    const float* bn_m   = (const float*)d_in[16];
    const float* bn_v   = (const float*)d_in[17];
    float* out = (float*)d_out;

    float *xp, *xpt, *cam, *aff, *loc, *gg, *lf, *qry, *oat, *key, *glob, *valT, *bconf, *bnS, *bnT;
    cudaGetSymbolAddress((void**)&xp,    g_xp);
    cudaGetSymbolAddress((void**)&xpt,   g_xpt);
    cudaGetSymbolAddress((void**)&cam,   g_cam);
    cudaGetSymbolAddress((void**)&aff,   g_aff);
    cudaGetSymbolAddress((void**)&loc,   g_local);
    cudaGetSymbolAddress((void**)&gg,    g_g);
    cudaGetSymbolAddress((void**)&lf,    g_lf);
    cudaGetSymbolAddress((void**)&qry,   g_query);
    cudaGetSymbolAddress((void**)&oat,   g_oattn);
    cudaGetSymbolAddress((void**)&key,   g_key);
    cudaGetSymbolAddress((void**)&glob,  g_glob);
    cudaGetSymbolAddress((void**)&valT,  g_valT);
    cudaGetSymbolAddress((void**)&bconf, g_bconf);
    cudaGetSymbolAddress((void**)&bnS,   g_bnS);
    cudaGetSymbolAddress((void**)&bnT,   g_bnT);

    // BN constants
    prep_bn<<<1, 512>>>(bn_g, bn_b, bn_m, bn_v, bnS, bnT);

    // patch-split transposes
    make_xp<<<dim3(16, 32, 64), dim3(32, 8)>>>(x, xp, xpt);

    // cam^T[b,n,k,p] = w_cam @ x_p^T (+b_cam per row k)
    gemm(w_cam, xp, cam, 512, 1024, 512, 0, 524288, 524288, 64, 1, b_cam, 1);

    // pixel softmax over p (rows of 1024) + bin_conf = sigmoid(row mean)
    softmax_rows<true><<<32768, 256>>>(cam, bconf, 1024);

    // local[b,n,k,c] = (conf^T @ x_p) * bin_conf[k]
    gemm(cam, xpt, loc, 512, 512, 1024, 524288, 524288, 262144, 64, 1,
         nullptr, 0, bconf, 512);

    // GCN bin mix + residual relu
    gcn_mix<<<4096, 256>>>(loc, w_gcn1, gg);

    // local_feats = g @ w_gcn2^T
    gemm(gg, w_gcn2, lf, 32768, 512, 512, 0, 0, 0, 1);

    // glob = relu(fuse over bins + b_fuse)
    fuse_glob<<<4096, 256>>>(lf, w_fuse, b_fuse, glob);

    // query / key / value^T
    gemm(xp, w_q, qry, 65536, 256, 512, 0, 0, 0, 1, 1, b_q, 2);
    gemm(lf, w_k, key, 32768, 256, 512, 0, 0, 0, 1, 1, b_k, 2);
    gemm(w_v, glob, valT, 256, 512, 512, 0, 262144, 131072, 4, 1, b_v, 1);

    // aff = query @ key^T per (b,bin); softmax over k
    gemm(qry, key, aff, 1024, 512, 256, 262144, 131072, 524288, 64);
    softmax_rows<false><<<65536, 128>>>(aff, nullptr, 512);

    // out_attn = aff @ value  (value shared across bins: zdivB=16)
    gemm(aff, valT, oat, 1024, 256, 512, 524288, 131072, 262144, 64, 16);

    // final 1x1 conv + BN + relu + residual, patch-recover fused epilogue
    gemm(w_out, oat, nullptr, 512, 1024, 256, 0, 262144, 0, 64, 1,
         nullptr, 0, nullptr, 0, 2, x, bnS, bnT, out);
}

// round 3
// speedup vs baseline: 2.0607x; 1.2591x over previous
#include <cuda_runtime.h>
#include <math.h>

// ---------------- scratch (device globals; no allocations allowed) ----------
__device__ float g_xp   [33554432];   // [B,16,1024,512]  x patch-split, channel-last
__device__ float g_xpt  [33554432];   // [B,16,512,1024]  x patch-split, pixel-last
__device__ float g_cam  [33554432];   // [B,16,512,1024]  cam^T, then pixel_conf in-place
__device__ float g_aff  [33554432];   // [B,16,1024,512]
__device__ float g_local[16777216];   // [B,16,512,512]
__device__ float g_g    [16777216];   // relu(gcn1 mix + local)
__device__ float g_lf   [16777216];   // local_feats
__device__ float g_query[16777216];   // [B,16,1024,256]
__device__ float g_oattn[16777216];   // [B,16,1024,256]
__device__ float g_key  [ 8388608];   // [B,16,512,256]
__device__ float g_glob [ 1048576];   // [B,512,512]
__device__ float g_valT [  524288];   // [B,256,512]  value transposed
__device__ float g_bconf[   32768];   // [B,16,512]
__device__ float g_bnS  [     512];
__device__ float g_bnT  [     512];

// ---------------- small helpers --------------------------------------------
__device__ __forceinline__ float warpRedSum(float v){
#pragma unroll
    for (int o = 16; o; o >>= 1) v += __shfl_xor_sync(0xffffffffu, v, o);
    return v;
}
__device__ __forceinline__ float warpRedMax(float v){
#pragma unroll
    for (int o = 16; o; o >>= 1) v = fmaxf(v, __shfl_xor_sync(0xffffffffu, v, o));
    return v;
}
// pack two fp32 -> bf16x2 word, lo = first k, hi = second k
__device__ __forceinline__ unsigned pack_bf16(float lo, float hi){
    unsigned u;
    asm("cvt.rn.bf16x2.f32 %0, %1, %2;" : "=r"(u) : "f"(hi), "f"(lo));
    return u;
}
__device__ __forceinline__ void mma_bf16(float* d, const unsigned* a, const unsigned* b){
    asm volatile(
        "mma.sync.aligned.m16n8k16.row.col.f32.bf16.bf16.f32 "
        "{%0,%1,%2,%3}, {%4,%5,%6,%7}, {%8,%9}, {%0,%1,%2,%3};"
        : "+f"(d[0]), "+f"(d[1]), "+f"(d[2]), "+f"(d[3])
        : "r"(a[0]), "r"(a[1]), "r"(a[2]), "r"(a[3]), "r"(b[0]), "r"(b[1]));
}

// ---------------- BN constant prep ------------------------------------------
__global__ void prep_bn(const float* __restrict__ gam, const float* __restrict__ bet,
                        const float* __restrict__ mean, const float* __restrict__ var,
                        float* __restrict__ S, float* __restrict__ T)
{
    int i = threadIdx.x;
    if (i < 512) {
        float inv = rsqrtf(var[i] + 1e-5f);
        float s = gam[i] * inv;
        S[i] = s;
        T[i] = bet[i] - mean[i] * s;
    }
}

// ---------------- patch-split transposes: x -> x_p ([p,c]) and x_pT ([c,p]) --
__global__ void make_xp(const float* __restrict__ x,
                        float* __restrict__ xp, float* __restrict__ xpt)
{
    __shared__ float t[32][33];
    const int ct = blockIdx.x * 32;
    const int rh = blockIdx.y;
    const int z  = blockIdx.z;            // b*16 + nbin
    const int b  = z >> 4, n = z & 15;
    const int h  = (n >> 2) * 32 + rh;
    const int wb = (n & 3) * 32;
    const int tx = threadIdx.x, ty = threadIdx.y;

    const float* xb = x + ((((long long)b * 512 + ct) * 128 + h) * 128 + wb);
#pragma unroll
    for (int i = 0; i < 4; i++) {
        int cc = ty + 8 * i;
        t[cc][tx] = xb[(long long)cc * 16384 + tx];
    }
    __syncthreads();
    float* xpb = xp + (((long long)z * 1024 + rh * 32) * 512) + ct;
#pragma unroll
    for (int i = 0; i < 4; i++) {
        int rw = ty + 8 * i;
        xpb[(long long)rw * 512 + tx] = t[tx][rw];
    }
    float* xptb = xpt + (((long long)z * 512 + ct) * 1024) + rh * 32;
#pragma unroll
    for (int i = 0; i < 4; i++) {
        int cc = ty + 8 * i;
        xptb[(long long)cc * 1024 + tx] = t[cc][tx];
    }
}

// ---------------- row softmax (in place), optional sigmoid(mean) side output -
template<bool HASCONF>
__global__ void softmax_rows(float* __restrict__ data, float* __restrict__ conf, int rowlen)
{
    const int tid = threadIdx.x;
    const long long r = blockIdx.x;
    float4* row = (float4*)(data + r * (long long)rowlen);
    float4 v = row[tid];

    float lmax = fmaxf(fmaxf(v.x, v.y), fmaxf(v.z, v.w));
    float lsum = v.x + v.y + v.z + v.w;

    __shared__ float sm[32], ss[32];
    const int lane = tid & 31, wid = tid >> 5, nw = blockDim.x >> 5;
    float wmax = warpRedMax(lmax), wsum = warpRedSum(lsum);
    if (lane == 0) { sm[wid] = wmax; ss[wid] = wsum; }
    __syncthreads();
    if (tid < 32) {
        float a  = (tid < nw) ? sm[tid] : -3.402823466e38f;
        float b2 = (tid < nw) ? ss[tid] : 0.f;
        a  = warpRedMax(a);
        b2 = warpRedSum(b2);
        if (tid == 0) { sm[0] = a; ss[0] = b2; }
    }
    __syncthreads();
    const float rmax = sm[0];
    if (HASCONF && tid == 0)
        conf[r] = 1.f / (1.f + expf(-ss[0] / (float)rowlen));
    __syncthreads();

    float4 e;
    e.x = expf(v.x - rmax); e.y = expf(v.y - rmax);
    e.z = expf(v.z - rmax); e.w = expf(v.w - rmax);
    float les = e.x + e.y + e.z + e.w;
    float ws = warpRedSum(les);
    if (lane == 0) ss[wid] = ws;
    __syncthreads();
    if (tid < 32) {
        float b2 = (tid < nw) ? ss[tid] : 0.f;
        b2 = warpRedSum(b2);
        if (tid == 0) ss[0] = b2;
    }
    __syncthreads();
    const float inv = 1.f / ss[0];
    e.x *= inv; e.y *= inv; e.z *= inv; e.w *= inv;
    row[tid] = e;
}

// ---------------- GCN 16x16 bin mix + residual relu -------------------------
__global__ void gcn_mix(const float* __restrict__ local, const float* __restrict__ w1,
                        float* __restrict__ g)
{
    __shared__ float w[256];
    if (threadIdx.x < 256) w[threadIdx.x] = w1[threadIdx.x];
    __syncthreads();
    long long j = (long long)blockIdx.x * blockDim.x + threadIdx.x;
    const int b = (int)(j >> 18);
    const long long jj = j & 262143;
    const float* base = local + ((long long)b << 22) + jj;
    float v[16];
#pragma unroll
    for (int m = 0; m < 16; m++) v[m] = base[(long long)m << 18];
    float* ob = g + ((long long)b << 22) + jj;
#pragma unroll
    for (int n = 0; n < 16; n++) {
        float s = v[n];
#pragma unroll
        for (int m = 0; m < 16; m++) s = fmaf(w[n * 16 + m], v[m], s);
        ob[(long long)n << 18] = fmaxf(s, 0.f);
    }
}

// ---------------- fuse: glob[b,j] = relu(b_fuse + sum_m w_fuse[m]*lf[b,m,j]) -
__global__ void fuse_glob(const float* __restrict__ lf, const float* __restrict__ wf,
                          const float* __restrict__ bf, float* __restrict__ glob)
{
    __shared__ float w[16];
    __shared__ float b0;
    if (threadIdx.x < 16) w[threadIdx.x] = wf[threadIdx.x];
    if (threadIdx.x == 16) b0 = bf[0];
    __syncthreads();
    long long j = (long long)blockIdx.x * blockDim.x + threadIdx.x;
    const int b = (int)(j >> 18);
    const long long jj = j & 262143;
    const float* base = lf + ((long long)b << 22) + jj;
    float s = b0;
#pragma unroll
    for (int m = 0; m < 16; m++) s = fmaf(w[m], base[(long long)m << 18], s);
    glob[((long long)b << 18) + jj] = fmaxf(s, 0.f);
}

// ---------------- TN GEMM via mma.sync bf16 ----------------------------------
// C[m,n] = sum_kd A[m,kd]*B[n,kd]. fp32 in/out, bf16 operands, fp32 accumulate.
// CTA tile 128x128, k-tile 16 double-buffered (smem holds bf16x2-packed words:
// [kpair][row]). 8 warps, warp tile 32(M) x 64(N), mma m16n8k16.
// M,N multiples of 128; Kd multiple of 16.
__global__ __launch_bounds__(256) void gemm_tn_tc(
    const float* __restrict__ Ab, const float* __restrict__ Bb, float* __restrict__ Cb,
    int N, int Kd,
    long long sA, long long sB, long long sC, int zdivB,
    const float* __restrict__ bias, int biasMode,
    const float* __restrict__ rowscale, long long sScale,
    int epi,
    const float* __restrict__ resid, const float* __restrict__ bnS,
    const float* __restrict__ bnT, float* __restrict__ outp)
{
    __shared__ unsigned As[2][8][132];   // [kpair 0..7][m row]
    __shared__ unsigned Bs[2][8][132];   // [kpair 0..7][n col]

    const int z = blockIdx.z;
    const float* A = Ab + (long long)z * sA;
    const float* B = Bb + (long long)(z / zdivB) * sB;

    const int tid  = threadIdx.x;
    const int m0   = blockIdx.y * 128;
    const int n0   = blockIdx.x * 128;

    const int lane = tid & 31;
    const int warp = tid >> 5;
    const int gq   = lane >> 2;      // 0..7
    const int tq   = lane & 3;       // 0..3
    const int m0w  = (warp >> 1) * 32;
    const int n0w  = (warp & 1) * 64;

    // global->smem: row r = tid>>1 (0..127), k window kc..kc+7 (kpairs kp..kp+3)
    const int r  = tid >> 1;
    const int kc = (tid & 1) * 8;
    const int kp = (tid & 1) * 4;
    const float* Ag = A + (long long)(m0 + r) * Kd + kc;
    const float* Bg = B + (long long)(n0 + r) * Kd + kc;

    float acc[2][8][4];
#pragma unroll
    for (int i = 0; i < 2; i++)
#pragma unroll
        for (int j = 0; j < 8; j++)
#pragma unroll
            for (int q = 0; q < 4; q++) acc[i][j][q] = 0.f;

    float4 pa0 = *(const float4*)Ag;
    float4 pa1 = *(const float4*)(Ag + 4);
    float4 pb0 = *(const float4*)Bg;
    float4 pb1 = *(const float4*)(Bg + 4);

    // store tile 0
    {
        unsigned (*Sa)[132] = As[0];
        unsigned (*Sb)[132] = Bs[0];
        Sa[kp + 0][r] = pack_bf16(pa0.x, pa0.y);
        Sa[kp + 1][r] = pack_bf16(pa0.z, pa0.w);
        Sa[kp + 2][r] = pack_bf16(pa1.x, pa1.y);
        Sa[kp + 3][r] = pack_bf16(pa1.z, pa1.w);
        Sb[kp + 0][r] = pack_bf16(pb0.x, pb0.y);
        Sb[kp + 1][r] = pack_bf16(pb0.z, pb0.w);
        Sb[kp + 2][r] = pack_bf16(pb1.x, pb1.y);
        Sb[kp + 3][r] = pack_bf16(pb1.z, pb1.w);
    }
    __syncthreads();

    int s = 0;
    for (int k0 = 0; ; ) {
        const bool last = (k0 + 16 >= Kd);
        if (!last) {
            Ag += 16; Bg += 16;
            pa0 = *(const float4*)Ag; pa1 = *(const float4*)(Ag + 4);
            pb0 = *(const float4*)Bg; pb1 = *(const float4*)(Bg + 4);
        }
        // compute one k16 step from buffer s
        {
            unsigned af[2][4], bf[8][2];
#pragma unroll
            for (int mt = 0; mt < 2; mt++) {
                const int mr = m0w + mt * 16 + gq;
                af[mt][0] = As[s][tq    ][mr    ];
                af[mt][1] = As[s][tq    ][mr + 8];
                af[mt][2] = As[s][tq + 4][mr    ];
                af[mt][3] = As[s][tq + 4][mr + 8];
            }
#pragma unroll
            for (int nt = 0; nt < 8; nt++) {
                const int nc = n0w + nt * 8 + gq;
                bf[nt][0] = Bs[s][tq    ][nc];
                bf[nt][1] = Bs[s][tq + 4][nc];
            }
#pragma unroll
            for (int mt = 0; mt < 2; mt++)
#pragma unroll
                for (int nt = 0; nt < 8; nt++)
                    mma_bf16(acc[mt][nt], af[mt], bf[nt]);
        }
        if (last) break;
        k0 += 16;
        {
            unsigned (*Sa)[132] = As[s ^ 1];
            unsigned (*Sb)[132] = Bs[s ^ 1];
            Sa[kp + 0][r] = pack_bf16(pa0.x, pa0.y);
            Sa[kp + 1][r] = pack_bf16(pa0.z, pa0.w);
            Sa[kp + 2][r] = pack_bf16(pa1.x, pa1.y);
            Sa[kp + 3][r] = pack_bf16(pa1.z, pa1.w);
            Sb[kp + 0][r] = pack_bf16(pb0.x, pb0.y);
            Sb[kp + 1][r] = pack_bf16(pb0.z, pb0.w);
            Sb[kp + 2][r] = pack_bf16(pb1.x, pb1.y);
            Sb[kp + 3][r] = pack_bf16(pb1.z, pb1.w);
        }
        __syncthreads();
        s ^= 1;
    }

    // ---- epilogue ----
    // element (mt, h, nt, q): row = m0+m0w+mt*16+gq+h*8 ; col = n0+n0w+nt*8+2*tq+q
    if (biasMode == 1) {
#pragma unroll
        for (int mt = 0; mt < 2; mt++)
#pragma unroll
            for (int h = 0; h < 2; h++) {
                const float bb = bias[m0 + m0w + mt * 16 + gq + h * 8];
#pragma unroll
                for (int nt = 0; nt < 8; nt++) {
                    acc[mt][nt][h * 2 + 0] += bb;
                    acc[mt][nt][h * 2 + 1] += bb;
                }
            }
    } else if (biasMode == 2) {
#pragma unroll
        for (int nt = 0; nt < 8; nt++) {
            const int c0 = n0 + n0w + nt * 8 + 2 * tq;
            const float b0v = bias[c0], b1v = bias[c0 + 1];
#pragma unroll
            for (int mt = 0; mt < 2; mt++) {
                acc[mt][nt][0] += b0v; acc[mt][nt][1] += b1v;
                acc[mt][nt][2] += b0v; acc[mt][nt][3] += b1v;
            }
        }
    }
    if (rowscale) {
        const float* rs = rowscale + (long long)z * sScale;
#pragma unroll
        for (int mt = 0; mt < 2; mt++)
#pragma unroll
            for (int h = 0; h < 2; h++) {
                const float f = rs[m0 + m0w + mt * 16 + gq + h * 8];
#pragma unroll
                for (int nt = 0; nt < 8; nt++) {
                    acc[mt][nt][h * 2 + 0] *= f;
                    acc[mt][nt][h * 2 + 1] *= f;
                }
            }
    }

    if (epi == 0) {
        float* C = Cb + (long long)z * sC;
#pragma unroll
        for (int mt = 0; mt < 2; mt++)
#pragma unroll
            for (int h = 0; h < 2; h++) {
                const int row = m0 + m0w + mt * 16 + gq + h * 8;
                float* cp = C + (long long)row * N + n0 + n0w + 2 * tq;
#pragma unroll
                for (int nt = 0; nt < 8; nt++)
                    *(float2*)(cp + nt * 8) =
                        make_float2(acc[mt][nt][h * 2 + 0], acc[mt][nt][h * 2 + 1]);
            }
    } else {
        // final conv: row=channel co, col=p within bin z. BN+relu+residual,
        // patch-recover into [B,512,128,128].
        const int b = z >> 4, nbin = z & 15;
        const int hb = (nbin >> 2) * 32, wb = (nbin & 3) * 32;
#pragma unroll
        for (int mt = 0; mt < 2; mt++)
#pragma unroll
            for (int h2 = 0; h2 < 2; h2++) {
                const int co = m0 + m0w + mt * 16 + gq + h2 * 8;
                const float sc = bnS[co], tt = bnT[co];
                const long long cbase = ((long long)(b * 512 + co) * 128);
#pragma unroll
                for (int nt = 0; nt < 8; nt++) {
                    const int p = n0 + n0w + nt * 8 + 2 * tq;   // even
                    const int hh = hb + (p >> 5);
                    const int ww = wb + (p & 31);
                    const long long oi = (cbase + hh) * 128 + ww;
                    float2 rv = *(const float2*)(resid + oi);
                    float v0 = fmaxf(fmaf(acc[mt][nt][h2 * 2 + 0], sc, tt), 0.f);
                    float v1 = fmaxf(fmaf(acc[mt][nt][h2 * 2 + 1], sc, tt), 0.f);
                    *(float2*)(outp + oi) = make_float2(rv.x + v0, rv.y + v1);
                }
            }
    }
}

// ---------------- host side --------------------------------------------------
static void gemm(const float* A, const float* B, float* C, int M, int N, int Kd,
                 long long sA, long long sB, long long sC, int Z, int zdivB = 1,
                 const float* bias = nullptr, int biasMode = 0,
                 const float* rowscale = nullptr, long long sScale = 0,
                 int epi = 0, const float* resid = nullptr,
                 const float* bnS = nullptr, const float* bnT = nullptr,
                 float* outp = nullptr)
{
    dim3 grid(N / 128, M / 128, Z), block(256);
    gemm_tn_tc<<<grid, block>>>(A, B, C, N, Kd, sA, sB, sC, zdivB,
                                bias, biasMode, rowscale, sScale,
                                epi, resid, bnS, bnT, outp);
}

extern "C" void kernel_launch(void* const* d_in, const int* in_sizes, int n_in,
                              void* d_out, int out_size)
{
    const float* x      = (const float*)d_in[0];
    const float* w_cam  = (const float*)d_in[1];
    const float* b_cam  = (const float*)d_in[2];
    const float* w_gcn1 = (const float*)d_in[3];
    const float* w_gcn2 = (const float*)d_in[4];
    const float* w_fuse = (const float*)d_in[5];
    const float* b_fuse = (const float*)d_in[6];
    const float* w_q    = (const float*)d_in[7];
    const float* b_q    = (const float*)d_in[8];
    const float* w_k    = (const float*)d_in[9];
    const float* b_k    = (const float*)d_in[10];
    const float* w_v    = (const float*)d_in[11];
    const float* b_v    = (const float*)d_in[12];
    const float* w_out  = (const float*)d_in[13];
    const float* bn_g   = (const float*)d_in[14];
    const float* bn_b   = (const float*)d_in[15];
    const float* bn_m   = (const float*)d_in[16];
    const float* bn_v   = (const float*)d_in[17];
    float* out = (float*)d_out;

    float *xp, *xpt, *cam, *aff, *loc, *gg, *lf, *qry, *oat, *key, *glob, *valT, *bconf, *bnS, *bnT;
    cudaGetSymbolAddress((void**)&xp,    g_xp);
    cudaGetSymbolAddress((void**)&xpt,   g_xpt);
    cudaGetSymbolAddress((void**)&cam,   g_cam);
    cudaGetSymbolAddress((void**)&aff,   g_aff);
    cudaGetSymbolAddress((void**)&loc,   g_local);
    cudaGetSymbolAddress((void**)&gg,    g_g);
    cudaGetSymbolAddress((void**)&lf,    g_lf);
    cudaGetSymbolAddress((void**)&qry,   g_query);
    cudaGetSymbolAddress((void**)&oat,   g_oattn);
    cudaGetSymbolAddress((void**)&key,   g_key);
    cudaGetSymbolAddress((void**)&glob,  g_glob);
    cudaGetSymbolAddress((void**)&valT,  g_valT);
    cudaGetSymbolAddress((void**)&bconf, g_bconf);
    cudaGetSymbolAddress((void**)&bnS,   g_bnS);
    cudaGetSymbolAddress((void**)&bnT,   g_bnT);

    // BN constants
    prep_bn<<<1, 512>>>(bn_g, bn_b, bn_m, bn_v, bnS, bnT);

    // patch-split transposes
    make_xp<<<dim3(16, 32, 64), dim3(32, 8)>>>(x, xp, xpt);

    // cam^T[b,n,k,p] = w_cam @ x_p^T (+b_cam per row k)
    gemm(w_cam, xp, cam, 512, 1024, 512, 0, 524288, 524288, 64, 1, b_cam, 1);

    // pixel softmax over p (rows of 1024) + bin_conf = sigmoid(row mean)
    softmax_rows<true><<<32768, 256>>>(cam, bconf, 1024);

    // local[b,n,k,c] = (conf^T @ x_p) * bin_conf[k]
    gemm(cam, xpt, loc, 512, 512, 1024, 524288, 524288, 262144, 64, 1,
         nullptr, 0, bconf, 512);

    // GCN bin mix + residual relu
    gcn_mix<<<4096, 256>>>(loc, w_gcn1, gg);

    // local_feats = g @ w_gcn2^T
    gemm(gg, w_gcn2, lf, 32768, 512, 512, 0, 0, 0, 1);

    // glob = relu(fuse over bins + b_fuse)
    fuse_glob<<<4096, 256>>>(lf, w_fuse, b_fuse, glob);

    // query / key / value^T
    gemm(xp, w_q, qry, 65536, 256, 512, 0, 0, 0, 1, 1, b_q, 2);
    gemm(lf, w_k, key, 32768, 256, 512, 0, 0, 0, 1, 1, b_k, 2);
    gemm(w_v, glob, valT, 256, 512, 512, 0, 262144, 131072, 4, 1, b_v, 1);

    // aff = query @ key^T per (b,bin); softmax over k
    gemm(qry, key, aff, 1024, 512, 256, 262144, 131072, 524288, 64);
    softmax_rows<false><<<65536, 128>>>(aff, nullptr, 512);

    // out_attn = aff @ value  (value shared across bins: zdivB=16)
    gemm(aff, valT, oat, 1024, 256, 512, 524288, 131072, 262144, 64, 16);

    // final 1x1 conv + BN + relu + residual, patch-recover fused epilogue
    gemm(w_out, oat, nullptr, 512, 1024, 256, 0, 262144, 0, 64, 1,
         nullptr, 0, nullptr, 0, 2, x, bnS, bnT, out);
}

// round 4
// speedup vs baseline: 2.7072x; 1.3137x over previous
#include <cuda_runtime.h>
#include <cuda_bf16.h>
#include <math.h>

// ---------------- scratch (device globals; no allocations allowed) ----------
// bf16 intermediates (stored as unsigned short to be safe as __device__ arrays)
__device__ unsigned short g_xp   [33554432];   // [B,16,1024,512]
__device__ unsigned short g_xpt  [33554432];   // [B,16,512,1024]
__device__ unsigned short g_cam  [33554432];   // [B,16,512,1024] logits -> conf
__device__ unsigned short g_aff  [33554432];   // [B,16,1024,512]
__device__ unsigned short g_local[16777216];   // [B,16,512,512]
__device__ unsigned short g_g    [16777216];
__device__ unsigned short g_lf   [16777216];
__device__ unsigned short g_query[16777216];   // [B,16,1024,256]
__device__ unsigned short g_oattn[16777216];   // [B,16,1024,256]
__device__ unsigned short g_key  [ 8388608];   // [B,16,512,256]
__device__ unsigned short g_glob [ 1048576];   // [B,512,512]
__device__ unsigned short g_valT [  524288];   // [B,256,512]
__device__ unsigned short g_wbf  [ 1048576];   // packed bf16 weights (see offsets)
__device__ float g_bconf[32768];
__device__ float g_bnS  [512];
__device__ float g_bnT  [512];

// weight offsets inside g_wbf
#define W_CAM  0
#define W_GCN2 262144
#define W_Q    524288
#define W_K    655360
#define W_V    786432
#define W_OUT  917504

// ---------------- small helpers --------------------------------------------
__device__ __forceinline__ float warpRedSum(float v){
#pragma unroll
    for (int o = 16; o; o >>= 1) v += __shfl_xor_sync(0xffffffffu, v, o);
    return v;
}
__device__ __forceinline__ float warpRedMax(float v){
#pragma unroll
    for (int o = 16; o; o >>= 1) v = fmaxf(v, __shfl_xor_sync(0xffffffffu, v, o));
    return v;
}
__device__ __forceinline__ void mma_bf16(float* d, const unsigned* a, const unsigned* b){
    asm volatile(
        "mma.sync.aligned.m16n8k16.row.col.f32.bf16.bf16.f32 "
        "{%0,%1,%2,%3}, {%4,%5,%6,%7}, {%8,%9}, {%0,%1,%2,%3};"
        : "+f"(d[0]), "+f"(d[1]), "+f"(d[2]), "+f"(d[3])
        : "r"(a[0]), "r"(a[1]), "r"(a[2]), "r"(a[3]), "r"(b[0]), "r"(b[1]));
}

// ---------------- BN constant prep ------------------------------------------
__global__ void prep_bn(const float* __restrict__ gam, const float* __restrict__ bet,
                        const float* __restrict__ mean, const float* __restrict__ var,
                        float* __restrict__ S, float* __restrict__ T)
{
    int i = threadIdx.x;
    if (i < 512) {
        float inv = rsqrtf(var[i] + 1e-5f);
        float s = gam[i] * inv;
        S[i] = s;
        T[i] = bet[i] - mean[i] * s;
    }
}

// ---------------- weights fp32 -> bf16 ---------------------------------------
__global__ void cvt_weights(const float* __restrict__ wcam, const float* __restrict__ wgcn2,
                            const float* __restrict__ wq, const float* __restrict__ wk,
                            const float* __restrict__ wv, const float* __restrict__ wout,
                            __nv_bfloat16* __restrict__ dst)
{
    int i = blockIdx.x * blockDim.x + threadIdx.x;   // 0..1048575
    float v;
    if      (i < 262144)  v = wcam [i];
    else if (i < 524288)  v = wgcn2[i - 262144];
    else if (i < 655360)  v = wq   [i - 524288];
    else if (i < 786432)  v = wk   [i - 655360];
    else if (i < 917504)  v = wv   [i - 786432];
    else                  v = wout [i - 917504];
    dst[i] = __float2bfloat16(v);
}

// ---------------- patch-split transposes: x -> x_p ([p,c]) and x_pT ([c,p]) --
__global__ void make_xp(const float* __restrict__ x,
                        __nv_bfloat16* __restrict__ xp, __nv_bfloat16* __restrict__ xpt)
{
    __shared__ float t[32][33];
    const int ct = blockIdx.x * 32;
    const int rh = blockIdx.y;
    const int z  = blockIdx.z;            // b*16 + nbin
    const int b  = z >> 4, n = z & 15;
    const int h  = (n >> 2) * 32 + rh;
    const int wb = (n & 3) * 32;
    const int tx = threadIdx.x, ty = threadIdx.y;

    const float* xb = x + ((((long long)b * 512 + ct) * 128 + h) * 128 + wb);
#pragma unroll
    for (int i = 0; i < 4; i++) {
        int cc = ty + 8 * i;
        t[cc][tx] = xb[(long long)cc * 16384 + tx];
    }
    __syncthreads();
    __nv_bfloat16* xpb = xp + (((long long)z * 1024 + rh * 32) * 512) + ct;
#pragma unroll
    for (int i = 0; i < 4; i++) {
        int rw = ty + 8 * i;
        xpb[(long long)rw * 512 + tx] = __float2bfloat16(t[tx][rw]);
    }
    __nv_bfloat16* xptb = xpt + (((long long)z * 512 + ct) * 1024) + rh * 32;
#pragma unroll
    for (int i = 0; i < 4; i++) {
        int cc = ty + 8 * i;
        xptb[(long long)cc * 1024 + tx] = __float2bfloat16(t[cc][tx]);
    }
}

// ---------------- bf16 row softmax (in place), optional sigmoid(mean) -------
// blockDim.x = rowlen/8; each thread handles 8 bf16 (one uint4).
template<bool HASCONF>
__global__ void softmax_rows(__nv_bfloat16* __restrict__ data,
                             float* __restrict__ conf, int rowlen)
{
    const int tid = threadIdx.x;
    const long long r = blockIdx.x;
    uint4* row = (uint4*)(data + r * (long long)rowlen);
    uint4 v = row[tid];

    float2 f[4];
    f[0] = __bfloat1622float2(*(__nv_bfloat162*)&v.x);
    f[1] = __bfloat1622float2(*(__nv_bfloat162*)&v.y);
    f[2] = __bfloat1622float2(*(__nv_bfloat162*)&v.z);
    f[3] = __bfloat1622float2(*(__nv_bfloat162*)&v.w);

    float lmax = -3.402823466e38f, lsum = 0.f;
#pragma unroll
    for (int i = 0; i < 4; i++) {
        lmax = fmaxf(lmax, fmaxf(f[i].x, f[i].y));
        lsum += f[i].x + f[i].y;
    }

    __shared__ float sm[32], ss[32];
    const int lane = tid & 31, wid = tid >> 5, nw = blockDim.x >> 5;
    float wmax = warpRedMax(lmax), wsum = warpRedSum(lsum);
    if (lane == 0) { sm[wid] = wmax; ss[wid] = wsum; }
    __syncthreads();
    if (tid < 32) {
        float a  = (tid < nw) ? sm[tid] : -3.402823466e38f;
        float b2 = (tid < nw) ? ss[tid] : 0.f;
        a  = warpRedMax(a);
        b2 = warpRedSum(b2);
        if (tid == 0) { sm[0] = a; ss[0] = b2; }
    }
    __syncthreads();
    const float rmax = sm[0];
    if (HASCONF && tid == 0)
        conf[r] = 1.f / (1.f + expf(-ss[0] / (float)rowlen));
    __syncthreads();

    float les = 0.f;
#pragma unroll
    for (int i = 0; i < 4; i++) {
        f[i].x = expf(f[i].x - rmax);
        f[i].y = expf(f[i].y - rmax);
        les += f[i].x + f[i].y;
    }
    float ws = warpRedSum(les);
    if (lane == 0) ss[wid] = ws;
    __syncthreads();
    if (tid < 32) {
        float b2 = (tid < nw) ? ss[tid] : 0.f;
        b2 = warpRedSum(b2);
        if (tid == 0) ss[0] = b2;
    }
    __syncthreads();
    const float inv = 1.f / ss[0];
    uint4 o;
    __nv_bfloat162 p;
    p = __float22bfloat162_rn(make_float2(f[0].x * inv, f[0].y * inv)); o.x = *(unsigned*)&p;
    p = __float22bfloat162_rn(make_float2(f[1].x * inv, f[1].y * inv)); o.y = *(unsigned*)&p;
    p = __float22bfloat162_rn(make_float2(f[2].x * inv, f[2].y * inv)); o.z = *(unsigned*)&p;
    p = __float22bfloat162_rn(make_float2(f[3].x * inv, f[3].y * inv)); o.w = *(unsigned*)&p;
    row[tid] = o;
}

// ---------------- GCN 16x16 bin mix + residual relu (bf16x2 words) ----------
__global__ void gcn_mix(const __nv_bfloat162* __restrict__ local,
                        const float* __restrict__ w1, __nv_bfloat162* __restrict__ g)
{
    __shared__ float w[256];
    if (threadIdx.x < 256) w[threadIdx.x] = w1[threadIdx.x];
    __syncthreads();
    long long j = (long long)blockIdx.x * blockDim.x + threadIdx.x;  // 0..524287
    const int b = (int)(j >> 17);
    const long long jj = j & 131071;
    const __nv_bfloat162* base = local + ((long long)b << 21) + jj;
    float2 v[16];
#pragma unroll
    for (int m = 0; m < 16; m++) v[m] = __bfloat1622float2(base[(long long)m << 17]);
    __nv_bfloat162* ob = g + ((long long)b << 21) + jj;
#pragma unroll
    for (int n = 0; n < 16; n++) {
        float sx = v[n].x, sy = v[n].y;
#pragma unroll
        for (int m = 0; m < 16; m++) {
            sx = fmaf(w[n * 16 + m], v[m].x, sx);
            sy = fmaf(w[n * 16 + m], v[m].y, sy);
        }
        ob[(long long)n << 17] = __float22bfloat162_rn(make_float2(fmaxf(sx, 0.f), fmaxf(sy, 0.f)));
    }
}

// ---------------- fuse: glob = relu(b_fuse + sum_m w_fuse[m]*lf[m]) ----------
__global__ void fuse_glob(const __nv_bfloat162* __restrict__ lf,
                          const float* __restrict__ wf, const float* __restrict__ bf,
                          __nv_bfloat162* __restrict__ glob)
{
    __shared__ float w[16];
    __shared__ float b0;
    if (threadIdx.x < 16) w[threadIdx.x] = wf[threadIdx.x];
    if (threadIdx.x == 16) b0 = bf[0];
    __syncthreads();
    long long j = (long long)blockIdx.x * blockDim.x + threadIdx.x;  // 0..524287
    const int b = (int)(j >> 17);
    const long long jj = j & 131071;
    const __nv_bfloat162* base = lf + ((long long)b << 21) + jj;
    float sx = b0, sy = b0;
#pragma unroll
    for (int m = 0; m < 16; m++) {
        float2 v = __bfloat1622float2(base[(long long)m << 17]);
        sx = fmaf(w[m], v.x, sx);
        sy = fmaf(w[m], v.y, sy);
    }
    glob[((long long)b << 17) + jj] =
        __float22bfloat162_rn(make_float2(fmaxf(sx, 0.f), fmaxf(sy, 0.f)));
}

// ---------------- TN GEMM, bf16 in / bf16 or fused-fp32 out ------------------
// C[m,n] = sum_kd A[m,kd]*B[n,kd]. Operands bf16 row-major (K contiguous).
// CTA tile 128x128, k-tile 16 double-buffered, smem packed [kpair][row].
// 8 warps, warp tile 32x64, mma m16n8k16, fp32 accumulate.
__global__ __launch_bounds__(256) void gemm_tn_tc(
    const __nv_bfloat16* __restrict__ Ab, const __nv_bfloat16* __restrict__ Bb,
    __nv_bfloat16* __restrict__ Cb,
    int N, int Kd,
    long long sA, long long sB, long long sC, int zdivB,
    const float* __restrict__ bias, int biasMode,
    const float* __restrict__ rowscale, long long sScale,
    int epi,
    const float* __restrict__ resid, const float* __restrict__ bnS,
    const float* __restrict__ bnT, float* __restrict__ outp)
{
    __shared__ unsigned As[2][8][132];   // [kpair 0..7][m row]
    __shared__ unsigned Bs[2][8][132];   // [kpair 0..7][n col]

    const int z = blockIdx.z;
    const __nv_bfloat16* A = Ab + (long long)z * sA;
    const __nv_bfloat16* B = Bb + (long long)(z / zdivB) * sB;

    const int tid  = threadIdx.x;
    const int m0   = blockIdx.y * 128;
    const int n0   = blockIdx.x * 128;

    const int lane = tid & 31;
    const int warp = tid >> 5;
    const int gq   = lane >> 2;      // 0..7
    const int tq   = lane & 3;       // 0..3
    const int m0w  = (warp >> 1) * 32;
    const int n0w  = (warp & 1) * 64;

    // global->smem: row r = tid>>1, k window kc..kc+7 = kpairs kp..kp+3
    const int r  = tid >> 1;
    const int kc = (tid & 1) * 8;
    const int kp = (tid & 1) * 4;
    const __nv_bfloat16* Ag = A + (long long)(m0 + r) * Kd + kc;
    const __nv_bfloat16* Bg = B + (long long)(n0 + r) * Kd + kc;

    float acc[2][8][4];
#pragma unroll
    for (int i = 0; i < 2; i++)
#pragma unroll
        for (int j = 0; j < 8; j++)
#pragma unroll
            for (int q = 0; q < 4; q++) acc[i][j][q] = 0.f;

    uint4 pa = *(const uint4*)Ag;
    uint4 pb = *(const uint4*)Bg;

    // store tile 0
    {
        unsigned (*Sa)[132] = As[0];
        unsigned (*Sb)[132] = Bs[0];
        Sa[kp + 0][r] = pa.x; Sa[kp + 1][r] = pa.y;
        Sa[kp + 2][r] = pa.z; Sa[kp + 3][r] = pa.w;
        Sb[kp + 0][r] = pb.x; Sb[kp + 1][r] = pb.y;
        Sb[kp + 2][r] = pb.z; Sb[kp + 3][r] = pb.w;
    }
    __syncthreads();

    int s = 0;
    for (int k0 = 0; ; ) {
        const bool last = (k0 + 16 >= Kd);
        if (!last) {
            Ag += 16; Bg += 16;
            pa = *(const uint4*)Ag;
            pb = *(const uint4*)Bg;
        }
        {
            unsigned af[2][4], bf[8][2];
#pragma unroll
            for (int mt = 0; mt < 2; mt++) {
                const int mr = m0w + mt * 16 + gq;
                af[mt][0] = As[s][tq    ][mr    ];
                af[mt][1] = As[s][tq    ][mr + 8];
                af[mt][2] = As[s][tq + 4][mr    ];
                af[mt][3] = As[s][tq + 4][mr + 8];
            }
#pragma unroll
            for (int nt = 0; nt < 8; nt++) {
                const int nc = n0w + nt * 8 + gq;
                bf[nt][0] = Bs[s][tq    ][nc];
                bf[nt][1] = Bs[s][tq + 4][nc];
            }
#pragma unroll
            for (int mt = 0; mt < 2; mt++)
#pragma unroll
                for (int nt = 0; nt < 8; nt++)
                    mma_bf16(acc[mt][nt], af[mt], bf[nt]);
        }
        if (last) break;
        k0 += 16;
        {
            unsigned (*Sa)[132] = As[s ^ 1];
            unsigned (*Sb)[132] = Bs[s ^ 1];
            Sa[kp + 0][r] = pa.x; Sa[kp + 1][r] = pa.y;
            Sa[kp + 2][r] = pa.z; Sa[kp + 3][r] = pa.w;
            Sb[kp + 0][r] = pb.x; Sb[kp + 1][r] = pb.y;
            Sb[kp + 2][r] = pb.z; Sb[kp + 3][r] = pb.w;
        }
        __syncthreads();
        s ^= 1;
    }

    // ---- epilogue ----
    // element (mt,h,nt,q): row = m0+m0w+mt*16+gq+h*8 ; col = n0+n0w+nt*8+2*tq+q
    if (biasMode == 1) {
#pragma unroll
        for (int mt = 0; mt < 2; mt++)
#pragma unroll
            for (int h = 0; h < 2; h++) {
                const float bb = bias[m0 + m0w + mt * 16 + gq + h * 8];
#pragma unroll
                for (int nt = 0; nt < 8; nt++) {
                    acc[mt][nt][h * 2 + 0] += bb;
                    acc[mt][nt][h * 2 + 1] += bb;
                }
            }
    } else if (biasMode == 2) {
#pragma unroll
        for (int nt = 0; nt < 8; nt++) {
            const int c0 = n0 + n0w + nt * 8 + 2 * tq;
            const float b0v = bias[c0], b1v = bias[c0 + 1];
#pragma unroll
            for (int mt = 0; mt < 2; mt++) {
                acc[mt][nt][0] += b0v; acc[mt][nt][1] += b1v;
                acc[mt][nt][2] += b0v; acc[mt][nt][3] += b1v;
            }
        }
    }
    if (rowscale) {
        const float* rs = rowscale + (long long)z * sScale;
#pragma unroll
        for (int mt = 0; mt < 2; mt++)
#pragma unroll
            for (int h = 0; h < 2; h++) {
                const float f = rs[m0 + m0w + mt * 16 + gq + h * 8];
#pragma unroll
                for (int nt = 0; nt < 8; nt++) {
                    acc[mt][nt][h * 2 + 0] *= f;
                    acc[mt][nt][h * 2 + 1] *= f;
                }
            }
    }

    if (epi == 0) {
        __nv_bfloat16* C = Cb + (long long)z * sC;
#pragma unroll
        for (int mt = 0; mt < 2; mt++)
#pragma unroll
            for (int h = 0; h < 2; h++) {
                const int row = m0 + m0w + mt * 16 + gq + h * 8;
                __nv_bfloat16* cp = C + (long long)row * N + n0 + n0w + 2 * tq;
#pragma unroll
                for (int nt = 0; nt < 8; nt++)
                    *(__nv_bfloat162*)(cp + nt * 8) =
                        __float22bfloat162_rn(
                            make_float2(acc[mt][nt][h * 2 + 0], acc[mt][nt][h * 2 + 1]));
            }
    } else {
        // final conv: row=channel co, col=p within bin z. BN+relu+residual,
        // patch-recover into [B,512,128,128] fp32.
        const int b = z >> 4, nbin = z & 15;
        const int hb = (nbin >> 2) * 32, wb = (nbin & 3) * 32;
#pragma unroll
        for (int mt = 0; mt < 2; mt++)
#pragma unroll
            for (int h2 = 0; h2 < 2; h2++) {
                const int co = m0 + m0w + mt * 16 + gq + h2 * 8;
                const float sc = bnS[co], tt = bnT[co];
                const long long cbase = ((long long)(b * 512 + co) * 128);
#pragma unroll
                for (int nt = 0; nt < 8; nt++) {
                    const int p = n0 + n0w + nt * 8 + 2 * tq;   // even
                    const int hh = hb + (p >> 5);
                    const int ww = wb + (p & 31);
                    const long long oi = (cbase + hh) * 128 + ww;
                    float2 rv = *(const float2*)(resid + oi);
                    float v0 = fmaxf(fmaf(acc[mt][nt][h2 * 2 + 0], sc, tt), 0.f);
                    float v1 = fmaxf(fmaf(acc[mt][nt][h2 * 2 + 1], sc, tt), 0.f);
                    *(float2*)(outp + oi) = make_float2(rv.x + v0, rv.y + v1);
                }
            }
    }
}

// ---------------- host side --------------------------------------------------
static void gemm(const __nv_bfloat16* A, const __nv_bfloat16* B, __nv_bfloat16* C,
                 int M, int N, int Kd,
                 long long sA, long long sB, long long sC, int Z, int zdivB = 1,
                 const float* bias = nullptr, int biasMode = 0,
                 const float* rowscale = nullptr, long long sScale = 0,
                 int epi = 0, const float* resid = nullptr,
                 const float* bnS = nullptr, const float* bnT = nullptr,
                 float* outp = nullptr)
{
    dim3 grid(N / 128, M / 128, Z), block(256);
    gemm_tn_tc<<<grid, block>>>(A, B, C, N, Kd, sA, sB, sC, zdivB,
                                bias, biasMode, rowscale, sScale,
                                epi, resid, bnS, bnT, outp);
}

extern "C" void kernel_launch(void* const* d_in, const int* in_sizes, int n_in,
                              void* d_out, int out_size)
{
    const float* x      = (const float*)d_in[0];
    const float* w_cam  = (const float*)d_in[1];
    const float* b_cam  = (const float*)d_in[2];
    const float* w_gcn1 = (const float*)d_in[3];
    const float* w_gcn2 = (const float*)d_in[4];
    const float* w_fuse = (const float*)d_in[5];
    const float* b_fuse = (const float*)d_in[6];
    const float* w_q    = (const float*)d_in[7];
    const float* b_q    = (const float*)d_in[8];
    const float* w_k    = (const float*)d_in[9];
    const float* b_k    = (const float*)d_in[10];
    const float* w_v    = (const float*)d_in[11];
    const float* b_v    = (const float*)d_in[12];
    const float* w_out  = (const float*)d_in[13];
    const float* bn_g   = (const float*)d_in[14];
    const float* bn_b   = (const float*)d_in[15];
    const float* bn_m   = (const float*)d_in[16];
    const float* bn_v   = (const float*)d_in[17];
    float* out = (float*)d_out;

    __nv_bfloat16 *xp, *xpt, *cam, *aff, *loc, *gg, *lf, *qry, *oat, *key, *glob, *valT, *wbf;
    float *bconf, *bnS, *bnT;
    cudaGetSymbolAddress((void**)&xp,    g_xp);
    cudaGetSymbolAddress((void**)&xpt,   g_xpt);
    cudaGetSymbolAddress((void**)&cam,   g_cam);
    cudaGetSymbolAddress((void**)&aff,   g_aff);
    cudaGetSymbolAddress((void**)&loc,   g_local);
    cudaGetSymbolAddress((void**)&gg,    g_g);
    cudaGetSymbolAddress((void**)&lf,    g_lf);
    cudaGetSymbolAddress((void**)&qry,   g_query);
    cudaGetSymbolAddress((void**)&oat,   g_oattn);
    cudaGetSymbolAddress((void**)&key,   g_key);
    cudaGetSymbolAddress((void**)&glob,  g_glob);
    cudaGetSymbolAddress((void**)&valT,  g_valT);
    cudaGetSymbolAddress((void**)&wbf,   g_wbf);
    cudaGetSymbolAddress((void**)&bconf, g_bconf);
    cudaGetSymbolAddress((void**)&bnS,   g_bnS);
    cudaGetSymbolAddress((void**)&bnT,   g_bnT);

    // constants
    prep_bn<<<1, 512>>>(bn_g, bn_b, bn_m, bn_v, bnS, bnT);
    cvt_weights<<<4096, 256>>>(w_cam, w_gcn2, w_q, w_k, w_v, w_out, wbf);

    // patch-split transposes (fp32 -> bf16)
    make_xp<<<dim3(16, 32, 64), dim3(32, 8)>>>(x, xp, xpt);

    // cam^T[b,n,k,p] = w_cam @ x_p^T (+b_cam per row k)
    gemm(wbf + W_CAM, xp, cam, 512, 1024, 512, 0, 524288, 524288, 64, 1, b_cam, 1);

    // pixel softmax over p + bin_conf = sigmoid(row mean)
    softmax_rows<true><<<32768, 128>>>(cam, bconf, 1024);

    // local[b,n,k,c] = (conf^T @ x_p) * bin_conf[k]
    gemm(cam, xpt, loc, 512, 512, 1024, 524288, 524288, 262144, 64, 1,
         nullptr, 0, bconf, 512);

    // GCN bin mix + residual relu (bf16x2 words)
    gcn_mix<<<2048, 256>>>((const __nv_bfloat162*)loc, w_gcn1, (__nv_bfloat162*)gg);

    // local_feats = g @ w_gcn2^T
    gemm(gg, wbf + W_GCN2, lf, 32768, 512, 512, 0, 0, 0, 1);

    // glob = relu(fuse over bins + b_fuse)
    fuse_glob<<<2048, 256>>>((const __nv_bfloat162*)lf, w_fuse, b_fuse,
                             (__nv_bfloat162*)glob);

    // query / key / value^T
    gemm(xp, wbf + W_Q, qry, 65536, 256, 512, 0, 0, 0, 1, 1, b_q, 2);
    gemm(lf, wbf + W_K, key, 32768, 256, 512, 0, 0, 0, 1, 1, b_k, 2);
    gemm(wbf + W_V, glob, valT, 256, 512, 512, 0, 262144, 131072, 4, 1, b_v, 1);

    // aff = query @ key^T per (b,bin); softmax over k
    gemm(qry, key, aff, 1024, 512, 256, 262144, 131072, 524288, 64);
    softmax_rows<false><<<65536, 64>>>(aff, nullptr, 512);

    // out_attn = aff @ value (value shared across bins: zdivB=16)
    gemm(aff, valT, oat, 1024, 256, 512, 524288, 131072, 262144, 64, 16);

    // final 1x1 conv + BN + relu + residual, patch-recover fused epilogue
    gemm(wbf + W_OUT, oat, nullptr, 512, 1024, 256, 0, 262144, 0, 64, 1,
         nullptr, 0, nullptr, 0, 2, x, bnS, bnT, out);
}

// round 5
// speedup vs baseline: 3.3561x; 1.2397x over previous
#include <cuda_runtime.h>
#include <cuda_bf16.h>
#include <math.h>

// ---------------- scratch (device globals; no allocations allowed) ----------
__device__ unsigned short g_xp   [33554432];   // [B,16,1024,512]
__device__ unsigned short g_xpt  [33554432];   // [B,16,512,1024]
__device__ unsigned short g_cam  [33554432];   // [B,16,512,1024] logits -> conf
__device__ unsigned short g_aff  [33554432];   // [B,16,1024,512]
__device__ unsigned short g_local[16777216];   // [B,16,512,512]
__device__ unsigned short g_g    [16777216];
__device__ unsigned short g_lf   [16777216];
__device__ unsigned short g_query[16777216];   // [B,16,1024,256]
__device__ unsigned short g_oattn[16777216];   // [B,16,1024,256]
__device__ unsigned short g_key  [ 8388608];   // [B,16,512,256]
__device__ unsigned short g_glob [ 1048576];   // [B,512,512]
__device__ unsigned short g_valT [  524288];   // [B,256,512]
__device__ unsigned short g_wbf  [ 1048576];   // packed bf16 weights
__device__ float g_bconf[32768];
__device__ float g_bnS  [512];
__device__ float g_bnT  [512];

#define W_CAM  0
#define W_GCN2 262144
#define W_Q    524288
#define W_K    655360
#define W_V    786432
#define W_OUT  917504

// ---------------- small helpers --------------------------------------------
__device__ __forceinline__ float warpRedSum(float v){
#pragma unroll
    for (int o = 16; o; o >>= 1) v += __shfl_xor_sync(0xffffffffu, v, o);
    return v;
}
__device__ __forceinline__ float warpRedMax(float v){
#pragma unroll
    for (int o = 16; o; o >>= 1) v = fmaxf(v, __shfl_xor_sync(0xffffffffu, v, o));
    return v;
}
__device__ __forceinline__ void mma_bf16(float* d, const unsigned* a, const unsigned* b){
    asm volatile(
        "mma.sync.aligned.m16n8k16.row.col.f32.bf16.bf16.f32 "
        "{%0,%1,%2,%3}, {%4,%5,%6,%7}, {%8,%9}, {%0,%1,%2,%3};"
        : "+f"(d[0]), "+f"(d[1]), "+f"(d[2]), "+f"(d[3])
        : "r"(a[0]), "r"(a[1]), "r"(a[2]), "r"(a[3]), "r"(b[0]), "r"(b[1]));
}

// ---------------- BN constant prep ------------------------------------------
__global__ void prep_bn(const float* __restrict__ gam, const float* __restrict__ bet,
                        const float* __restrict__ mean, const float* __restrict__ var,
                        float* __restrict__ S, float* __restrict__ T)
{
    int i = threadIdx.x;
    if (i < 512) {
        float inv = rsqrtf(var[i] + 1e-5f);
        float s = gam[i] * inv;
        S[i] = s;
        T[i] = bet[i] - mean[i] * s;
    }
}

// ---------------- weights fp32 -> bf16 ---------------------------------------
__global__ void cvt_weights(const float* __restrict__ wcam, const float* __restrict__ wgcn2,
                            const float* __restrict__ wq, const float* __restrict__ wk,
                            const float* __restrict__ wv, const float* __restrict__ wout,
                            __nv_bfloat16* __restrict__ dst)
{
    int i = blockIdx.x * blockDim.x + threadIdx.x;   // 0..1048575
    float v;
    if      (i < 262144)  v = wcam [i];
    else if (i < 524288)  v = wgcn2[i - 262144];
    else if (i < 655360)  v = wq   [i - 524288];
    else if (i < 786432)  v = wk   [i - 655360];
    else if (i < 917504)  v = wv   [i - 786432];
    else                  v = wout [i - 917504];
    dst[i] = __float2bfloat16(v);
}

// ---------------- patch-split transposes -------------------------------------
__global__ void make_xp(const float* __restrict__ x,
                        __nv_bfloat16* __restrict__ xp, __nv_bfloat16* __restrict__ xpt)
{
    __shared__ float t[32][33];
    const int ct = blockIdx.x * 32;
    const int rh = blockIdx.y;
    const int z  = blockIdx.z;            // b*16 + nbin
    const int b  = z >> 4, n = z & 15;
    const int h  = (n >> 2) * 32 + rh;
    const int wb = (n & 3) * 32;
    const int tx = threadIdx.x, ty = threadIdx.y;

    const float* xb = x + ((((long long)b * 512 + ct) * 128 + h) * 128 + wb);
#pragma unroll
    for (int i = 0; i < 4; i++) {
        int cc = ty + 8 * i;
        t[cc][tx] = xb[(long long)cc * 16384 + tx];
    }
    __syncthreads();
    __nv_bfloat16* xpb = xp + (((long long)z * 1024 + rh * 32) * 512) + ct;
#pragma unroll
    for (int i = 0; i < 4; i++) {
        int rw = ty + 8 * i;
        xpb[(long long)rw * 512 + tx] = __float2bfloat16(t[tx][rw]);
    }
    __nv_bfloat16* xptb = xpt + (((long long)z * 512 + ct) * 1024) + rh * 32;
#pragma unroll
    for (int i = 0; i < 4; i++) {
        int cc = ty + 8 * i;
        xptb[(long long)cc * 1024 + tx] = __float2bfloat16(t[cc][tx]);
    }
}

// ---------------- bf16 row softmax (in place), optional sigmoid(mean) -------
template<bool HASCONF>
__global__ void softmax_rows(__nv_bfloat16* __restrict__ data,
                             float* __restrict__ conf, int rowlen)
{
    const int tid = threadIdx.x;
    const long long r = blockIdx.x;
    uint4* row = (uint4*)(data + r * (long long)rowlen);
    uint4 v = row[tid];

    float2 f[4];
    f[0] = __bfloat1622float2(*(__nv_bfloat162*)&v.x);
    f[1] = __bfloat1622float2(*(__nv_bfloat162*)&v.y);
    f[2] = __bfloat1622float2(*(__nv_bfloat162*)&v.z);
    f[3] = __bfloat1622float2(*(__nv_bfloat162*)&v.w);

    float lmax = -3.402823466e38f, lsum = 0.f;
#pragma unroll
    for (int i = 0; i < 4; i++) {
        lmax = fmaxf(lmax, fmaxf(f[i].x, f[i].y));
        lsum += f[i].x + f[i].y;
    }

    __shared__ float sm[32], ss[32];
    const int lane = tid & 31, wid = tid >> 5, nw = blockDim.x >> 5;
    float wmax = warpRedMax(lmax), wsum = warpRedSum(lsum);
    if (lane == 0) { sm[wid] = wmax; ss[wid] = wsum; }
    __syncthreads();
    if (tid < 32) {
        float a  = (tid < nw) ? sm[tid] : -3.402823466e38f;
        float b2 = (tid < nw) ? ss[tid] : 0.f;
        a  = warpRedMax(a);
        b2 = warpRedSum(b2);
        if (tid == 0) { sm[0] = a; ss[0] = b2; }
    }
    __syncthreads();
    const float rmax = sm[0];
    if (HASCONF && tid == 0)
        conf[r] = 1.f / (1.f + expf(-ss[0] / (float)rowlen));
    __syncthreads();

    float les = 0.f;
#pragma unroll
    for (int i = 0; i < 4; i++) {
        f[i].x = expf(f[i].x - rmax);
        f[i].y = expf(f[i].y - rmax);
        les += f[i].x + f[i].y;
    }
    float ws = warpRedSum(les);
    if (lane == 0) ss[wid] = ws;
    __syncthreads();
    if (tid < 32) {
        float b2 = (tid < nw) ? ss[tid] : 0.f;
        b2 = warpRedSum(b2);
        if (tid == 0) ss[0] = b2;
    }
    __syncthreads();
    const float inv = 1.f / ss[0];
    uint4 o;
    __nv_bfloat162 p;
    p = __float22bfloat162_rn(make_float2(f[0].x * inv, f[0].y * inv)); o.x = *(unsigned*)&p;
    p = __float22bfloat162_rn(make_float2(f[1].x * inv, f[1].y * inv)); o.y = *(unsigned*)&p;
    p = __float22bfloat162_rn(make_float2(f[2].x * inv, f[2].y * inv)); o.z = *(unsigned*)&p;
    p = __float22bfloat162_rn(make_float2(f[3].x * inv, f[3].y * inv)); o.w = *(unsigned*)&p;
    row[tid] = o;
}

// ---------------- GCN 16x16 bin mix + residual relu (bf16x2 words) ----------
__global__ void gcn_mix(const __nv_bfloat162* __restrict__ local,
                        const float* __restrict__ w1, __nv_bfloat162* __restrict__ g)
{
    __shared__ float w[256];
    if (threadIdx.x < 256) w[threadIdx.x] = w1[threadIdx.x];
    __syncthreads();
    long long j = (long long)blockIdx.x * blockDim.x + threadIdx.x;
    const int b = (int)(j >> 17);
    const long long jj = j & 131071;
    const __nv_bfloat162* base = local + ((long long)b << 21) + jj;
    float2 v[16];
#pragma unroll
    for (int m = 0; m < 16; m++) v[m] = __bfloat1622float2(base[(long long)m << 17]);
    __nv_bfloat162* ob = g + ((long long)b << 21) + jj;
#pragma unroll
    for (int n = 0; n < 16; n++) {
        float sx = v[n].x, sy = v[n].y;
#pragma unroll
        for (int m = 0; m < 16; m++) {
            sx = fmaf(w[n * 16 + m], v[m].x, sx);
            sy = fmaf(w[n * 16 + m], v[m].y, sy);
        }
        ob[(long long)n << 17] = __float22bfloat162_rn(make_float2(fmaxf(sx, 0.f), fmaxf(sy, 0.f)));
    }
}

// ---------------- fuse: glob = relu(b_fuse + sum_m w_fuse[m]*lf[m]) ----------
__global__ void fuse_glob(const __nv_bfloat162* __restrict__ lf,
                          const float* __restrict__ wf, const float* __restrict__ bf,
                          __nv_bfloat162* __restrict__ glob)
{
    __shared__ float w[16];
    __shared__ float b0;
    if (threadIdx.x < 16) w[threadIdx.x] = wf[threadIdx.x];
    if (threadIdx.x == 16) b0 = bf[0];
    __syncthreads();
    long long j = (long long)blockIdx.x * blockDim.x + threadIdx.x;
    const int b = (int)(j >> 17);
    const long long jj = j & 131071;
    const __nv_bfloat162* base = lf + ((long long)b << 21) + jj;
    float sx = b0, sy = b0;
#pragma unroll
    for (int m = 0; m < 16; m++) {
        float2 v = __bfloat1622float2(base[(long long)m << 17]);
        sx = fmaf(w[m], v.x, sx);
        sy = fmaf(w[m], v.y, sy);
    }
    glob[((long long)b << 17) + jj] =
        __float22bfloat162_rn(make_float2(fmaxf(sx, 0.f), fmaxf(sy, 0.f)));
}

// ---------------- TN GEMM, bf16 in / bf16 or fused-fp32 out ------------------
// CTA tile 128x128, k-tile 16 double-buffered, smem packed [kpair][row].
// 8 warps, warp tile 32x64, mma m16n8k16, fp32 accumulate.
// __launch_bounds__(256,2): cap 128 regs -> 2 CTAs/SM (occupancy fix).
__global__ __launch_bounds__(256, 2) void gemm_tn_tc(
    const __nv_bfloat16* __restrict__ Ab, const __nv_bfloat16* __restrict__ Bb,
    __nv_bfloat16* __restrict__ Cb,
    int N, int Kd,
    long long sA, long long sB, long long sC, int zdivB,
    const float* __restrict__ bias, int biasMode,
    const float* __restrict__ rowscale, long long sScale,
    int epi,
    const float* __restrict__ resid, const float* __restrict__ bnS,
    const float* __restrict__ bnT, float* __restrict__ outp)
{
    __shared__ unsigned As[2][8][132];   // [kpair 0..7][m row]
    __shared__ unsigned Bs[2][8][132];   // [kpair 0..7][n col]

    const int z = blockIdx.z;
    const __nv_bfloat16* A = Ab + (long long)z * sA;
    const __nv_bfloat16* B = Bb + (long long)(z / zdivB) * sB;

    const int tid  = threadIdx.x;
    const int m0   = blockIdx.y * 128;
    const int n0   = blockIdx.x * 128;

    const int lane = tid & 31;
    const int warp = tid >> 5;
    const int gq   = lane >> 2;      // 0..7
    const int tq   = lane & 3;       // 0..3
    const int m0w  = (warp >> 1) * 32;
    const int n0w  = (warp & 1) * 64;

    const int r  = tid >> 1;
    const int kc = (tid & 1) * 8;
    const int kp = (tid & 1) * 4;
    const __nv_bfloat16* Ag = A + (long long)(m0 + r) * Kd + kc;
    const __nv_bfloat16* Bg = B + (long long)(n0 + r) * Kd + kc;

    float acc[2][8][4];
#pragma unroll
    for (int i = 0; i < 2; i++)
#pragma unroll
        for (int j = 0; j < 8; j++)
#pragma unroll
            for (int q = 0; q < 4; q++) acc[i][j][q] = 0.f;

    uint4 pa = *(const uint4*)Ag;
    uint4 pb = *(const uint4*)Bg;

    {
        unsigned (*Sa)[132] = As[0];
        unsigned (*Sb)[132] = Bs[0];
        Sa[kp + 0][r] = pa.x; Sa[kp + 1][r] = pa.y;
        Sa[kp + 2][r] = pa.z; Sa[kp + 3][r] = pa.w;
        Sb[kp + 0][r] = pb.x; Sb[kp + 1][r] = pb.y;
        Sb[kp + 2][r] = pb.z; Sb[kp + 3][r] = pb.w;
    }
    __syncthreads();

    int s = 0;
    for (int k0 = 0; ; ) {
        const bool last = (k0 + 16 >= Kd);
        if (!last) {
            Ag += 16; Bg += 16;
            pa = *(const uint4*)Ag;
            pb = *(const uint4*)Bg;
        }
        {
            unsigned af[2][4], bf[8][2];
#pragma unroll
            for (int mt = 0; mt < 2; mt++) {
                const int mr = m0w + mt * 16 + gq;
                af[mt][0] = As[s][tq    ][mr    ];
                af[mt][1] = As[s][tq    ][mr + 8];
                af[mt][2] = As[s][tq + 4][mr    ];
                af[mt][3] = As[s][tq + 4][mr + 8];
            }
#pragma unroll
            for (int nt = 0; nt < 8; nt++) {
                const int nc = n0w + nt * 8 + gq;
                bf[nt][0] = Bs[s][tq    ][nc];
                bf[nt][1] = Bs[s][tq + 4][nc];
            }
#pragma unroll
            for (int mt = 0; mt < 2; mt++)
#pragma unroll
                for (int nt = 0; nt < 8; nt++)
                    mma_bf16(acc[mt][nt], af[mt], bf[nt]);
        }
        if (last) break;
        k0 += 16;
        {
            unsigned (*Sa)[132] = As[s ^ 1];
            unsigned (*Sb)[132] = Bs[s ^ 1];
            Sa[kp + 0][r] = pa.x; Sa[kp + 1][r] = pa.y;
            Sa[kp + 2][r] = pa.z; Sa[kp + 3][r] = pa.w;
            Sb[kp + 0][r] = pb.x; Sb[kp + 1][r] = pb.y;
            Sb[kp + 2][r] = pb.z; Sb[kp + 3][r] = pb.w;
        }
        __syncthreads();
        s ^= 1;
    }

    // ---- epilogue ----
    if (biasMode == 1) {
#pragma unroll
        for (int mt = 0; mt < 2; mt++)
#pragma unroll
            for (int h = 0; h < 2; h++) {
                const float bb = bias[m0 + m0w + mt * 16 + gq + h * 8];
#pragma unroll
                for (int nt = 0; nt < 8; nt++) {
                    acc[mt][nt][h * 2 + 0] += bb;
                    acc[mt][nt][h * 2 + 1] += bb;
                }
            }
    } else if (biasMode == 2) {
#pragma unroll
        for (int nt = 0; nt < 8; nt++) {
            const int c0 = n0 + n0w + nt * 8 + 2 * tq;
            const float b0v = bias[c0], b1v = bias[c0 + 1];
#pragma unroll
            for (int mt = 0; mt < 2; mt++) {
                acc[mt][nt][0] += b0v; acc[mt][nt][1] += b1v;
                acc[mt][nt][2] += b0v; acc[mt][nt][3] += b1v;
            }
        }
    }
    if (rowscale) {
        const float* rs = rowscale + (long long)z * sScale;
#pragma unroll
        for (int mt = 0; mt < 2; mt++)
#pragma unroll
            for (int h = 0; h < 2; h++) {
                const float f = rs[m0 + m0w + mt * 16 + gq + h * 8];
#pragma unroll
                for (int nt = 0; nt < 8; nt++) {
                    acc[mt][nt][h * 2 + 0] *= f;
                    acc[mt][nt][h * 2 + 1] *= f;
                }
            }
    }

    if (epi == 0) {
        __nv_bfloat16* C = Cb + (long long)z * sC;
#pragma unroll
        for (int mt = 0; mt < 2; mt++)
#pragma unroll
            for (int h = 0; h < 2; h++) {
                const int row = m0 + m0w + mt * 16 + gq + h * 8;
                __nv_bfloat16* cp = C + (long long)row * N + n0 + n0w + 2 * tq;
#pragma unroll
                for (int nt = 0; nt < 8; nt++)
                    *(__nv_bfloat162*)(cp + nt * 8) =
                        __float22bfloat162_rn(
                            make_float2(acc[mt][nt][h * 2 + 0], acc[mt][nt][h * 2 + 1]));
            }
    } else {
        const int b = z >> 4, nbin = z & 15;
        const int hb = (nbin >> 2) * 32, wb = (nbin & 3) * 32;
#pragma unroll
        for (int mt = 0; mt < 2; mt++)
#pragma unroll
            for (int h2 = 0; h2 < 2; h2++) {
                const int co = m0 + m0w + mt * 16 + gq + h2 * 8;
                const float sc = bnS[co], tt = bnT[co];
                const long long cbase = ((long long)(b * 512 + co) * 128);
#pragma unroll
                for (int nt = 0; nt < 8; nt++) {
                    const int p = n0 + n0w + nt * 8 + 2 * tq;   // even
                    const int hh = hb + (p >> 5);
                    const int ww = wb + (p & 31);
                    const long long oi = (cbase + hh) * 128 + ww;
                    float2 rv = *(const float2*)(resid + oi);
                    float v0 = fmaxf(fmaf(acc[mt][nt][h2 * 2 + 0], sc, tt), 0.f);
                    float v1 = fmaxf(fmaf(acc[mt][nt][h2 * 2 + 1], sc, tt), 0.f);
                    *(float2*)(outp + oi) = make_float2(rv.x + v0, rv.y + v1);
                }
            }
    }
}

// ---------------- host side --------------------------------------------------
static void gemm(const __nv_bfloat16* A, const __nv_bfloat16* B, __nv_bfloat16* C,
                 int M, int N, int Kd,
                 long long sA, long long sB, long long sC, int Z, int zdivB = 1,
                 const float* bias = nullptr, int biasMode = 0,
                 const float* rowscale = nullptr, long long sScale = 0,
                 int epi = 0, const float* resid = nullptr,
                 const float* bnS = nullptr, const float* bnT = nullptr,
                 float* outp = nullptr)
{
    dim3 grid(N / 128, M / 128, Z), block(256);
    gemm_tn_tc<<<grid, block>>>(A, B, C, N, Kd, sA, sB, sC, zdivB,
                                bias, biasMode, rowscale, sScale,
                                epi, resid, bnS, bnT, outp);
}

extern "C" void kernel_launch(void* const* d_in, const int* in_sizes, int n_in,
                              void* d_out, int out_size)
{
    const float* x      = (const float*)d_in[0];
    const float* w_cam  = (const float*)d_in[1];
    const float* b_cam  = (const float*)d_in[2];
    const float* w_gcn1 = (const float*)d_in[3];
    const float* w_gcn2 = (const float*)d_in[4];
    const float* w_fuse = (const float*)d_in[5];
    const float* b_fuse = (const float*)d_in[6];
    const float* w_q    = (const float*)d_in[7];
    const float* b_q    = (const float*)d_in[8];
    const float* w_k    = (const float*)d_in[9];
    const float* b_k    = (const float*)d_in[10];
    const float* w_v    = (const float*)d_in[11];
    const float* b_v    = (const float*)d_in[12];
    const float* w_out  = (const float*)d_in[13];
    const float* bn_g   = (const float*)d_in[14];
    const float* bn_b   = (const float*)d_in[15];
    const float* bn_m   = (const float*)d_in[16];
    const float* bn_v   = (const float*)d_in[17];
    float* out = (float*)d_out;

    __nv_bfloat16 *xp, *xpt, *cam, *aff, *loc, *gg, *lf, *qry, *oat, *key, *glob, *valT, *wbf;
    float *bconf, *bnS, *bnT;
    cudaGetSymbolAddress((void**)&xp,    g_xp);
    cudaGetSymbolAddress((void**)&xpt,   g_xpt);
    cudaGetSymbolAddress((void**)&cam,   g_cam);
    cudaGetSymbolAddress((void**)&aff,   g_aff);
    cudaGetSymbolAddress((void**)&loc,   g_local);
    cudaGetSymbolAddress((void**)&gg,    g_g);
    cudaGetSymbolAddress((void**)&lf,    g_lf);
    cudaGetSymbolAddress((void**)&qry,   g_query);
    cudaGetSymbolAddress((void**)&oat,   g_oattn);
    cudaGetSymbolAddress((void**)&key,   g_key);
    cudaGetSymbolAddress((void**)&glob,  g_glob);
    cudaGetSymbolAddress((void**)&valT,  g_valT);
    cudaGetSymbolAddress((void**)&wbf,   g_wbf);
    cudaGetSymbolAddress((void**)&bconf, g_bconf);
    cudaGetSymbolAddress((void**)&bnS,   g_bnS);
    cudaGetSymbolAddress((void**)&bnT,   g_bnT);

    // constants
    prep_bn<<<1, 512>>>(bn_g, bn_b, bn_m, bn_v, bnS, bnT);
    cvt_weights<<<4096, 256>>>(w_cam, w_gcn2, w_q, w_k, w_v, w_out, wbf);

    // patch-split transposes (fp32 -> bf16)
    make_xp<<<dim3(16, 32, 64), dim3(32, 8)>>>(x, xp, xpt);

    // cam^T[b,n,k,p] = w_cam @ x_p^T (+b_cam per row k)
    gemm(wbf + W_CAM, xp, cam, 512, 1024, 512, 0, 524288, 524288, 64, 1, b_cam, 1);

    // pixel softmax over p + bin_conf = sigmoid(row mean)
    softmax_rows<true><<<32768, 128>>>(cam, bconf, 1024);

    // local[b,n,k,c] = (conf^T @ x_p) * bin_conf[k]
    gemm(cam, xpt, loc, 512, 512, 1024, 524288, 524288, 262144, 64, 1,
         nullptr, 0, bconf, 512);

    // GCN bin mix + residual relu
    gcn_mix<<<2048, 256>>>((const __nv_bfloat162*)loc, w_gcn1, (__nv_bfloat162*)gg);

    // local_feats = g @ w_gcn2^T
    gemm(gg, wbf + W_GCN2, lf, 32768, 512, 512, 0, 0, 0, 1);

    // glob = relu(fuse over bins + b_fuse)
    fuse_glob<<<2048, 256>>>((const __nv_bfloat162*)lf, w_fuse, b_fuse,
                             (__nv_bfloat162*)glob);

    // query / key / value^T
    gemm(xp, wbf + W_Q, qry, 65536, 256, 512, 0, 0, 0, 1, 1, b_q, 2);
    gemm(lf, wbf + W_K, key, 32768, 256, 512, 0, 0, 0, 1, 1, b_k, 2);
    gemm(wbf + W_V, glob, valT, 256, 512, 512, 0, 262144, 131072, 4, 1, b_v, 1);

    // aff = query @ key^T per (b,bin); softmax over k
    gemm(qry, key, aff, 1024, 512, 256, 262144, 131072, 524288, 64);
    softmax_rows<false><<<65536, 64>>>(aff, nullptr, 512);

    // out_attn = aff @ value (value shared across bins: zdivB=16)
    gemm(aff, valT, oat, 1024, 256, 512, 524288, 131072, 262144, 64, 16);

    // final 1x1 conv + BN + relu + residual, patch-recover fused epilogue
    gemm(wbf + W_OUT, oat, nullptr, 512, 1024, 256, 0, 262144, 0, 64, 1,
         nullptr, 0, nullptr, 0, 2, x, bnS, bnT, out);
}

// round 6
// speedup vs baseline: 4.5556x; 1.3574x over previous
#include <cuda_runtime.h>
#include <cuda_bf16.h>
#include <math.h>

// ---------------- scratch (device globals; no allocations allowed) ----------
__device__ unsigned short g_xp   [33554432];   // [B,16,1024,512]
__device__ unsigned short g_xpt  [33554432];   // [B,16,512,1024]
__device__ unsigned short g_cam  [33554432];   // [B,16,512,1024] logits -> conf
__device__ unsigned short g_aff  [33554432];   // [B,16,1024,512]
__device__ unsigned short g_local[16777216];   // [B,16,512,512]
__device__ unsigned short g_g    [16777216];
__device__ unsigned short g_lf   [16777216];
__device__ unsigned short g_query[16777216];   // [B,16,1024,256]
__device__ unsigned short g_oattn[16777216];   // [B,16,1024,256]
__device__ unsigned short g_key  [ 8388608];   // [B,16,512,256]
__device__ unsigned short g_glob [ 1048576];   // [B,512,512]
__device__ unsigned short g_valT [  524288];   // [B,256,512]
__device__ unsigned short g_wbf  [ 1048576];   // packed bf16 weights
__device__ float g_bconf[32768];
__device__ float g_bnS  [512];
__device__ float g_bnT  [512];

#define W_CAM  0
#define W_GCN2 262144
#define W_Q    524288
#define W_K    655360
#define W_V    786432
#define W_OUT  917504

// ---------------- small helpers --------------------------------------------
__device__ __forceinline__ float warpRedSum(float v){
#pragma unroll
    for (int o = 16; o; o >>= 1) v += __shfl_xor_sync(0xffffffffu, v, o);
    return v;
}
__device__ __forceinline__ float warpRedMax(float v){
#pragma unroll
    for (int o = 16; o; o >>= 1) v = fmaxf(v, __shfl_xor_sync(0xffffffffu, v, o));
    return v;
}
__device__ __forceinline__ void mma_bf16(float* d, const unsigned* a, const unsigned* b){
    asm volatile(
        "mma.sync.aligned.m16n8k16.row.col.f32.bf16.bf16.f32 "
        "{%0,%1,%2,%3}, {%4,%5,%6,%7}, {%8,%9}, {%0,%1,%2,%3};"
        : "+f"(d[0]), "+f"(d[1]), "+f"(d[2]), "+f"(d[3])
        : "r"(a[0]), "r"(a[1]), "r"(a[2]), "r"(a[3]), "r"(b[0]), "r"(b[1]));
}
__device__ __forceinline__ void ldsm_x4(unsigned& r0, unsigned& r1,
                                        unsigned& r2, unsigned& r3, unsigned addr){
    asm volatile("ldmatrix.sync.aligned.m8n8.x4.shared.b16 {%0,%1,%2,%3}, [%4];"
                 : "=r"(r0), "=r"(r1), "=r"(r2), "=r"(r3) : "r"(addr));
}

// ---------------- BN constant prep ------------------------------------------
__global__ void prep_bn(const float* __restrict__ gam, const float* __restrict__ bet,
                        const float* __restrict__ mean, const float* __restrict__ var,
                        float* __restrict__ S, float* __restrict__ T)
{
    int i = threadIdx.x;
    if (i < 512) {
        float inv = rsqrtf(var[i] + 1e-5f);
        float s = gam[i] * inv;
        S[i] = s;
        T[i] = bet[i] - mean[i] * s;
    }
}

// ---------------- weights fp32 -> bf16 ---------------------------------------
__global__ void cvt_weights(const float* __restrict__ wcam, const float* __restrict__ wgcn2,
                            const float* __restrict__ wq, const float* __restrict__ wk,
                            const float* __restrict__ wv, const float* __restrict__ wout,
                            __nv_bfloat16* __restrict__ dst)
{
    int i = blockIdx.x * blockDim.x + threadIdx.x;   // 0..1048575
    float v;
    if      (i < 262144)  v = wcam [i];
    else if (i < 524288)  v = wgcn2[i - 262144];
    else if (i < 655360)  v = wq   [i - 524288];
    else if (i < 786432)  v = wk   [i - 655360];
    else if (i < 917504)  v = wv   [i - 786432];
    else                  v = wout [i - 917504];
    dst[i] = __float2bfloat16(v);
}

// ---------------- patch-split transposes -------------------------------------
__global__ void make_xp(const float* __restrict__ x,
                        __nv_bfloat16* __restrict__ xp, __nv_bfloat16* __restrict__ xpt)
{
    __shared__ float t[32][33];
    const int ct = blockIdx.x * 32;
    const int rh = blockIdx.y;
    const int z  = blockIdx.z;            // b*16 + nbin
    const int b  = z >> 4, n = z & 15;
    const int h  = (n >> 2) * 32 + rh;
    const int wb = (n & 3) * 32;
    const int tx = threadIdx.x, ty = threadIdx.y;

    const float* xb = x + ((((long long)b * 512 + ct) * 128 + h) * 128 + wb);
#pragma unroll
    for (int i = 0; i < 4; i++) {
        int cc = ty + 8 * i;
        t[cc][tx] = xb[(long long)cc * 16384 + tx];
    }
    __syncthreads();
    __nv_bfloat16* xpb = xp + (((long long)z * 1024 + rh * 32) * 512) + ct;
#pragma unroll
    for (int i = 0; i < 4; i++) {
        int rw = ty + 8 * i;
        xpb[(long long)rw * 512 + tx] = __float2bfloat16(t[tx][rw]);
    }
    __nv_bfloat16* xptb = xpt + (((long long)z * 512 + ct) * 1024) + rh * 32;
#pragma unroll
    for (int i = 0; i < 4; i++) {
        int cc = ty + 8 * i;
        xptb[(long long)cc * 1024 + tx] = __float2bfloat16(t[cc][tx]);
    }
}

// ---------------- bf16 row softmax (in place), optional sigmoid(mean) -------
template<bool HASCONF>
__global__ void softmax_rows(__nv_bfloat16* __restrict__ data,
                             float* __restrict__ conf, int rowlen)
{
    const int tid = threadIdx.x;
    const long long r = blockIdx.x;
    uint4* row = (uint4*)(data + r * (long long)rowlen);
    uint4 v = row[tid];

    float2 f[4];
    f[0] = __bfloat1622float2(*(__nv_bfloat162*)&v.x);
    f[1] = __bfloat1622float2(*(__nv_bfloat162*)&v.y);
    f[2] = __bfloat1622float2(*(__nv_bfloat162*)&v.z);
    f[3] = __bfloat1622float2(*(__nv_bfloat162*)&v.w);

    float lmax = -3.402823466e38f, lsum = 0.f;
#pragma unroll
    for (int i = 0; i < 4; i++) {
        lmax = fmaxf(lmax, fmaxf(f[i].x, f[i].y));
        lsum += f[i].x + f[i].y;
    }

    __shared__ float sm[32], ss[32];
    const int lane = tid & 31, wid = tid >> 5, nw = blockDim.x >> 5;
    float wmax = warpRedMax(lmax), wsum = warpRedSum(lsum);
    if (lane == 0) { sm[wid] = wmax; ss[wid] = wsum; }
    __syncthreads();
    if (tid < 32) {
        float a  = (tid < nw) ? sm[tid] : -3.402823466e38f;
        float b2 = (tid < nw) ? ss[tid] : 0.f;
        a  = warpRedMax(a);
        b2 = warpRedSum(b2);
        if (tid == 0) { sm[0] = a; ss[0] = b2; }
    }
    __syncthreads();
    const float rmax = sm[0];
    if (HASCONF && tid == 0)
        conf[r] = 1.f / (1.f + expf(-ss[0] / (float)rowlen));
    __syncthreads();

    float les = 0.f;
#pragma unroll
    for (int i = 0; i < 4; i++) {
        f[i].x = expf(f[i].x - rmax);
        f[i].y = expf(f[i].y - rmax);
        les += f[i].x + f[i].y;
    }
    float ws = warpRedSum(les);
    if (lane == 0) ss[wid] = ws;
    __syncthreads();
    if (tid < 32) {
        float b2 = (tid < nw) ? ss[tid] : 0.f;
        b2 = warpRedSum(b2);
        if (tid == 0) ss[0] = b2;
    }
    __syncthreads();
    const float inv = 1.f / ss[0];
    uint4 o;
    __nv_bfloat162 p;
    p = __float22bfloat162_rn(make_float2(f[0].x * inv, f[0].y * inv)); o.x = *(unsigned*)&p;
    p = __float22bfloat162_rn(make_float2(f[1].x * inv, f[1].y * inv)); o.y = *(unsigned*)&p;
    p = __float22bfloat162_rn(make_float2(f[2].x * inv, f[2].y * inv)); o.z = *(unsigned*)&p;
    p = __float22bfloat162_rn(make_float2(f[3].x * inv, f[3].y * inv)); o.w = *(unsigned*)&p;
    row[tid] = o;
}

// ---------------- GCN 16x16 bin mix + residual relu (bf16x2 words) ----------
__global__ void gcn_mix(const __nv_bfloat162* __restrict__ local,
                        const float* __restrict__ w1, __nv_bfloat162* __restrict__ g)
{
    __shared__ float w[256];
    if (threadIdx.x < 256) w[threadIdx.x] = w1[threadIdx.x];
    __syncthreads();
    long long j = (long long)blockIdx.x * blockDim.x + threadIdx.x;
    const int b = (int)(j >> 17);
    const long long jj = j & 131071;
    const __nv_bfloat162* base = local + ((long long)b << 21) + jj;
    float2 v[16];
#pragma unroll
    for (int m = 0; m < 16; m++) v[m] = __bfloat1622float2(base[(long long)m << 17]);
    __nv_bfloat162* ob = g + ((long long)b << 21) + jj;
#pragma unroll
    for (int n = 0; n < 16; n++) {
        float sx = v[n].x, sy = v[n].y;
#pragma unroll
        for (int m = 0; m < 16; m++) {
            sx = fmaf(w[n * 16 + m], v[m].x, sx);
            sy = fmaf(w[n * 16 + m], v[m].y, sy);
        }
        ob[(long long)n << 17] = __float22bfloat162_rn(make_float2(fmaxf(sx, 0.f), fmaxf(sy, 0.f)));
    }
}

// ---------------- fuse: glob = relu(b_fuse + sum_m w_fuse[m]*lf[m]) ----------
__global__ void fuse_glob(const __nv_bfloat162* __restrict__ lf,
                          const float* __restrict__ wf, const float* __restrict__ bf,
                          __nv_bfloat162* __restrict__ glob)
{
    __shared__ float w[16];
    __shared__ float b0;
    if (threadIdx.x < 16) w[threadIdx.x] = wf[threadIdx.x];
    if (threadIdx.x == 16) b0 = bf[0];
    __syncthreads();
    long long j = (long long)blockIdx.x * blockDim.x + threadIdx.x;
    const int b = (int)(j >> 17);
    const long long jj = j & 131071;
    const __nv_bfloat162* base = lf + ((long long)b << 21) + jj;
    float sx = b0, sy = b0;
#pragma unroll
    for (int m = 0; m < 16; m++) {
        float2 v = __bfloat1622float2(base[(long long)m << 17]);
        sx = fmaf(w[m], v.x, sx);
        sy = fmaf(w[m], v.y, sy);
    }
    glob[((long long)b << 17) + jj] =
        __float22bfloat162_rn(make_float2(fmaxf(sx, 0.f), fmaxf(sy, 0.f)));
}

// ---------------- TN GEMM, bf16, ldmatrix + swizzled smem --------------------
// C[m,n] = sum_kd A[m,kd]*B[n,kd]. CTA tile 128x128, k-tile 32 double-buffered.
// smem: row-major [128 rows][32 bf16] per stage, 16B segs swizzled:
//   phys_seg = seg ^ ((row>>1)&3). STS.128 stores, ldmatrix.x4 fragment loads.
// 8 warps, warp tile 32x64, mma m16n8k16. M,N mult of 128; Kd mult of 32.
__global__ __launch_bounds__(256, 2) void gemm_tn_tc(
    const __nv_bfloat16* __restrict__ Ab, const __nv_bfloat16* __restrict__ Bb,
    __nv_bfloat16* __restrict__ Cb,
    int N, int Kd,
    long long sA, long long sB, long long sC, int zdivB,
    const float* __restrict__ bias, int biasMode,
    const float* __restrict__ rowscale, long long sScale,
    int epi,
    const float* __restrict__ resid, const float* __restrict__ bnS,
    const float* __restrict__ bnT, float* __restrict__ outp)
{
    __shared__ __align__(16) uint4 As[2][512];   // 2 stages x 128 rows x 4 segs
    __shared__ __align__(16) uint4 Bs[2][512];

    const int z = blockIdx.z;
    const __nv_bfloat16* A = Ab + (long long)z * sA;
    const __nv_bfloat16* B = Bb + (long long)(z / zdivB) * sB;

    const int tid  = threadIdx.x;
    const int m0   = blockIdx.y * 128;
    const int n0   = blockIdx.x * 128;

    const int lane = tid & 31;
    const int warp = tid >> 5;
    const int gq   = lane >> 2;
    const int tq   = lane & 3;
    const int m0w  = (warp >> 1) * 32;
    const int n0w  = (warp & 1) * 64;

    // global->smem: row r, k half kq (16 bf16 = 2 segs)
    const int r  = tid >> 1;
    const int kq = tid & 1;
    const int swz = (r >> 1) & 3;
    const int ph0 = (2 * kq)     ^ swz;
    const int ph1 = (2 * kq + 1) ^ swz;
    const __nv_bfloat16* Ag = A + (long long)(m0 + r) * Kd + kq * 16;
    const __nv_bfloat16* Bg = B + (long long)(n0 + r) * Kd + kq * 16;

    // ldmatrix lane addressing: matrix idx mi, within-matrix row wr
    const int mi  = lane >> 3;
    const int wr  = lane & 7;
    const int lrow = (mi & 1) * 8 + wr;   // + tile base row
    const int segS = mi >> 1;             // 0/1 within a k16 step

    const unsigned aBase = (unsigned)__cvta_generic_to_shared(As);
    const unsigned bBase = (unsigned)__cvta_generic_to_shared(Bs);

    float acc[2][8][4];
#pragma unroll
    for (int i = 0; i < 2; i++)
#pragma unroll
        for (int j = 0; j < 8; j++)
#pragma unroll
            for (int q = 0; q < 4; q++) acc[i][j][q] = 0.f;

    uint4 pa0 = *(const uint4*)Ag;
    uint4 pa1 = *(const uint4*)(Ag + 8);
    uint4 pb0 = *(const uint4*)Bg;
    uint4 pb1 = *(const uint4*)(Bg + 8);

    As[0][r * 4 + ph0] = pa0; As[0][r * 4 + ph1] = pa1;
    Bs[0][r * 4 + ph0] = pb0; Bs[0][r * 4 + ph1] = pb1;
    __syncthreads();

    int s = 0;
    for (int k0 = 0; ; ) {
        const bool last = (k0 + 32 >= Kd);
        if (!last) {
            Ag += 32; Bg += 32;
            pa0 = *(const uint4*)Ag; pa1 = *(const uint4*)(Ag + 8);
            pb0 = *(const uint4*)Bg; pb1 = *(const uint4*)(Bg + 8);
        }
#pragma unroll
        for (int kk = 0; kk < 2; kk++) {
            const int seg = 2 * kk + segS;
            unsigned af[2][4], bf[8][2];
#pragma unroll
            for (int mt = 0; mt < 2; mt++) {
                const int row = m0w + mt * 16 + lrow;
                const int phys = seg ^ ((row >> 1) & 3);
                ldsm_x4(af[mt][0], af[mt][1], af[mt][2], af[mt][3],
                        aBase + (unsigned)((s * 512 + row * 4 + phys) << 4));
            }
#pragma unroll
            for (int nt2 = 0; nt2 < 4; nt2++) {
                const int row = n0w + nt2 * 16 + lrow;
                const int phys = seg ^ ((row >> 1) & 3);
                unsigned t0, t1, t2, t3;
                ldsm_x4(t0, t1, t2, t3,
                        bBase + (unsigned)((s * 512 + row * 4 + phys) << 4));
                bf[2 * nt2][0] = t0; bf[2 * nt2 + 1][0] = t1;
                bf[2 * nt2][1] = t2; bf[2 * nt2 + 1][1] = t3;
            }
#pragma unroll
            for (int mt = 0; mt < 2; mt++)
#pragma unroll
                for (int nt = 0; nt < 8; nt++)
                    mma_bf16(acc[mt][nt], af[mt], bf[nt]);
        }
        if (last) break;
        k0 += 32;
        As[s ^ 1][r * 4 + ph0] = pa0; As[s ^ 1][r * 4 + ph1] = pa1;
        Bs[s ^ 1][r * 4 + ph0] = pb0; Bs[s ^ 1][r * 4 + ph1] = pb1;
        __syncthreads();
        s ^= 1;
    }

    // ---- epilogue ----
    // element (mt,h,nt,q): row = m0+m0w+mt*16+gq+h*8 ; col = n0+n0w+nt*8+2*tq+q
    if (biasMode == 1) {
#pragma unroll
        for (int mt = 0; mt < 2; mt++)
#pragma unroll
            for (int h = 0; h < 2; h++) {
                const float bb = bias[m0 + m0w + mt * 16 + gq + h * 8];
#pragma unroll
                for (int nt = 0; nt < 8; nt++) {
                    acc[mt][nt][h * 2 + 0] += bb;
                    acc[mt][nt][h * 2 + 1] += bb;
                }
            }
    } else if (biasMode == 2) {
#pragma unroll
        for (int nt = 0; nt < 8; nt++) {
            const int c0 = n0 + n0w + nt * 8 + 2 * tq;
            const float b0v = bias[c0], b1v = bias[c0 + 1];
#pragma unroll
            for (int mt = 0; mt < 2; mt++) {
                acc[mt][nt][0] += b0v; acc[mt][nt][1] += b1v;
                acc[mt][nt][2] += b0v; acc[mt][nt][3] += b1v;
            }
        }
    }
    if (rowscale) {
        const float* rs = rowscale + (long long)z * sScale;
#pragma unroll
        for (int mt = 0; mt < 2; mt++)
#pragma unroll
            for (int h = 0; h < 2; h++) {
                const float f = rs[m0 + m0w + mt * 16 + gq + h * 8];
#pragma unroll
                for (int nt = 0; nt < 8; nt++) {
                    acc[mt][nt][h * 2 + 0] *= f;
                    acc[mt][nt][h * 2 + 1] *= f;
                }
            }
    }

    if (epi == 0) {
        __nv_bfloat16* C = Cb + (long long)z * sC;
#pragma unroll
        for (int mt = 0; mt < 2; mt++)
#pragma unroll
            for (int h = 0; h < 2; h++) {
                const int row = m0 + m0w + mt * 16 + gq + h * 8;
                __nv_bfloat16* cp = C + (long long)row * N + n0 + n0w + 2 * tq;
#pragma unroll
                for (int nt = 0; nt < 8; nt++)
                    *(__nv_bfloat162*)(cp + nt * 8) =
                        __float22bfloat162_rn(
                            make_float2(acc[mt][nt][h * 2 + 0], acc[mt][nt][h * 2 + 1]));
            }
    } else {
        const int b = z >> 4, nbin = z & 15;
        const int hb = (nbin >> 2) * 32, wb = (nbin & 3) * 32;
#pragma unroll
        for (int mt = 0; mt < 2; mt++)
#pragma unroll
            for (int h2 = 0; h2 < 2; h2++) {
                const int co = m0 + m0w + mt * 16 + gq + h2 * 8;
                const float sc = bnS[co], tt = bnT[co];
                const long long cbase = ((long long)(b * 512 + co) * 128);
#pragma unroll
                for (int nt = 0; nt < 8; nt++) {
                    const int p = n0 + n0w + nt * 8 + 2 * tq;   // even
                    const int hh = hb + (p >> 5);
                    const int ww = wb + (p & 31);
                    const long long oi = (cbase + hh) * 128 + ww;
                    float2 rv = *(const float2*)(resid + oi);
                    float v0 = fmaxf(fmaf(acc[mt][nt][h2 * 2 + 0], sc, tt), 0.f);
                    float v1 = fmaxf(fmaf(acc[mt][nt][h2 * 2 + 1], sc, tt), 0.f);
                    *(float2*)(outp + oi) = make_float2(rv.x + v0, rv.y + v1);
                }
            }
    }
}

// ---------------- host side --------------------------------------------------
static void gemm(const __nv_bfloat16* A, const __nv_bfloat16* B, __nv_bfloat16* C,
                 int M, int N, int Kd,
                 long long sA, long long sB, long long sC, int Z, int zdivB = 1,
                 const float* bias = nullptr, int biasMode = 0,
                 const float* rowscale = nullptr, long long sScale = 0,
                 int epi = 0, const float* resid = nullptr,
                 const float* bnS = nullptr, const float* bnT = nullptr,
                 float* outp = nullptr)
{
    dim3 grid(N / 128, M / 128, Z), block(256);
    gemm_tn_tc<<<grid, block>>>(A, B, C, N, Kd, sA, sB, sC, zdivB,
                                bias, biasMode, rowscale, sScale,
                                epi, resid, bnS, bnT, outp);
}

extern "C" void kernel_launch(void* const* d_in, const int* in_sizes, int n_in,
                              void* d_out, int out_size)
{
    const float* x      = (const float*)d_in[0];
    const float* w_cam  = (const float*)d_in[1];
    const float* b_cam  = (const float*)d_in[2];
    const float* w_gcn1 = (const float*)d_in[3];
    const float* w_gcn2 = (const float*)d_in[4];
    const float* w_fuse = (const float*)d_in[5];
    const float* b_fuse = (const float*)d_in[6];
    const float* w_q    = (const float*)d_in[7];
    const float* b_q    = (const float*)d_in[8];
    const float* w_k    = (const float*)d_in[9];
    const float* b_k    = (const float*)d_in[10];
    const float* w_v    = (const float*)d_in[11];
    const float* b_v    = (const float*)d_in[12];
    const float* w_out  = (const float*)d_in[13];
    const float* bn_g   = (const float*)d_in[14];
    const float* bn_b   = (const float*)d_in[15];
    const float* bn_m   = (const float*)d_in[16];
    const float* bn_v   = (const float*)d_in[17];
    float* out = (float*)d_out;

    __nv_bfloat16 *xp, *xpt, *cam, *aff, *loc, *gg, *lf, *qry, *oat, *key, *glob, *valT, *wbf;
    float *bconf, *bnS, *bnT;
    cudaGetSymbolAddress((void**)&xp,    g_xp);
    cudaGetSymbolAddress((void**)&xpt,   g_xpt);
    cudaGetSymbolAddress((void**)&cam,   g_cam);
    cudaGetSymbolAddress((void**)&aff,   g_aff);
    cudaGetSymbolAddress((void**)&loc,   g_local);
    cudaGetSymbolAddress((void**)&gg,    g_g);
    cudaGetSymbolAddress((void**)&lf,    g_lf);
    cudaGetSymbolAddress((void**)&qry,   g_query);
    cudaGetSymbolAddress((void**)&oat,   g_oattn);
    cudaGetSymbolAddress((void**)&key,   g_key);
    cudaGetSymbolAddress((void**)&glob,  g_glob);
    cudaGetSymbolAddress((void**)&valT,  g_valT);
    cudaGetSymbolAddress((void**)&wbf,   g_wbf);
    cudaGetSymbolAddress((void**)&bconf, g_bconf);
    cudaGetSymbolAddress((void**)&bnS,   g_bnS);
    cudaGetSymbolAddress((void**)&bnT,   g_bnT);

    // constants
    prep_bn<<<1, 512>>>(bn_g, bn_b, bn_m, bn_v, bnS, bnT);
    cvt_weights<<<4096, 256>>>(w_cam, w_gcn2, w_q, w_k, w_v, w_out, wbf);

    // patch-split transposes (fp32 -> bf16)
    make_xp<<<dim3(16, 32, 64), dim3(32, 8)>>>(x, xp, xpt);

    // cam^T[b,n,k,p] = w_cam @ x_p^T (+b_cam per row k)
    gemm(wbf + W_CAM, xp, cam, 512, 1024, 512, 0, 524288, 524288, 64, 1, b_cam, 1);

    // pixel softmax over p + bin_conf = sigmoid(row mean)
    softmax_rows<true><<<32768, 128>>>(cam, bconf, 1024);

    // local[b,n,k,c] = (conf^T @ x_p) * bin_conf[k]
    gemm(cam, xpt, loc, 512, 512, 1024, 524288, 524288, 262144, 64, 1,
         nullptr, 0, bconf, 512);

    // GCN bin mix + residual relu
    gcn_mix<<<2048, 256>>>((const __nv_bfloat162*)loc, w_gcn1, (__nv_bfloat162*)gg);

    // local_feats = g @ w_gcn2^T
    gemm(gg, wbf + W_GCN2, lf, 32768, 512, 512, 0, 0, 0, 1);

    // glob = relu(fuse over bins + b_fuse)
    fuse_glob<<<2048, 256>>>((const __nv_bfloat162*)lf, w_fuse, b_fuse,
                             (__nv_bfloat162*)glob);

    // query / key / value^T
    gemm(xp, wbf + W_Q, qry, 65536, 256, 512, 0, 0, 0, 1, 1, b_q, 2);
    gemm(lf, wbf + W_K, key, 32768, 256, 512, 0, 0, 0, 1, 1, b_k, 2);
    gemm(wbf + W_V, glob, valT, 256, 512, 512, 0, 262144, 131072, 4, 1, b_v, 1);

    // aff = query @ key^T per (b,bin); softmax over k
    gemm(qry, key, aff, 1024, 512, 256, 262144, 131072, 524288, 64);
    softmax_rows<false><<<65536, 64>>>(aff, nullptr, 512);

    // out_attn = aff @ value (value shared across bins: zdivB=16)
    gemm(aff, valT, oat, 1024, 256, 512, 524288, 131072, 262144, 64, 16);

    // final 1x1 conv + BN + relu + residual, patch-recover fused epilogue
    gemm(wbf + W_OUT, oat, nullptr, 512, 1024, 256, 0, 262144, 0, 64, 1,
         nullptr, 0, nullptr, 0, 2, x, bnS, bnT, out);
}

// round 8
// speedup vs baseline: 4.9611x; 1.0890x over previous
#include <cuda_runtime.h>
#include <cuda_bf16.h>
#include <math.h>

// ---------------- scratch (device globals; no allocations allowed) ----------
__device__ unsigned short g_xp   [33554432];   // [B,16,1024,512]
__device__ unsigned short g_xpt  [33554432];   // [B,16,512,1024]
__device__ unsigned short g_cam  [33554432];   // [B,16,512,1024] logits -> conf
__device__ unsigned short g_aff  [33554432];   // [B,16,1024,512]
__device__ unsigned short g_local[16777216];   // [B,16,512,512]
__device__ unsigned short g_g    [16777216];
__device__ unsigned short g_lf   [16777216];
__device__ unsigned short g_query[16777216];   // [B,16,1024,256]
__device__ unsigned short g_oattn[16777216];   // [B,16,1024,256]
__device__ unsigned short g_key  [ 8388608];   // [B,16,512,256]
__device__ unsigned short g_glob [ 1048576];   // [B,512,512]
__device__ unsigned short g_valT [  524288];   // [B,256,512]
__device__ unsigned short g_wbf  [ 1048576];   // packed bf16 weights
__device__ float g_bconf[32768];
__device__ float g_bnS  [512];
__device__ float g_bnT  [512];

#define W_CAM  0
#define W_GCN2 262144
#define W_Q    524288
#define W_K    655360
#define W_V    786432
#define W_OUT  917504

// ---------------- small helpers --------------------------------------------
__device__ __forceinline__ float warpRedSum(float v){
#pragma unroll
    for (int o = 16; o; o >>= 1) v += __shfl_xor_sync(0xffffffffu, v, o);
    return v;
}
__device__ __forceinline__ float warpRedMax(float v){
#pragma unroll
    for (int o = 16; o; o >>= 1) v = fmaxf(v, __shfl_xor_sync(0xffffffffu, v, o));
    return v;
}
__device__ __forceinline__ void mma_bf16(float* d, const unsigned* a, const unsigned* b){
    asm volatile(
        "mma.sync.aligned.m16n8k16.row.col.f32.bf16.bf16.f32 "
        "{%0,%1,%2,%3}, {%4,%5,%6,%7}, {%8,%9}, {%0,%1,%2,%3};"
        : "+f"(d[0]), "+f"(d[1]), "+f"(d[2]), "+f"(d[3])
        : "r"(a[0]), "r"(a[1]), "r"(a[2]), "r"(a[3]), "r"(b[0]), "r"(b[1]));
}
__device__ __forceinline__ void ldsm_x4(unsigned& r0, unsigned& r1,
                                        unsigned& r2, unsigned& r3, unsigned addr){
    asm volatile("ldmatrix.sync.aligned.m8n8.x4.shared.b16 {%0,%1,%2,%3}, [%4];"
                 : "=r"(r0), "=r"(r1), "=r"(r2), "=r"(r3) : "r"(addr));
}
__device__ __forceinline__ void cp16(unsigned saddr, const void* gptr){
    asm volatile("cp.async.cg.shared.global [%0], [%1], 16;"
                 :: "r"(saddr), "l"(gptr) : "memory");
}

// ---------------- BN constant prep ------------------------------------------
__global__ void prep_bn(const float* __restrict__ gam, const float* __restrict__ bet,
                        const float* __restrict__ mean, const float* __restrict__ var,
                        float* __restrict__ S, float* __restrict__ T)
{
    int i = threadIdx.x;
    if (i < 512) {
        float inv = rsqrtf(var[i] + 1e-5f);
        float s = gam[i] * inv;
        S[i] = s;
        T[i] = bet[i] - mean[i] * s;
    }
}

// ---------------- weights fp32 -> bf16 ---------------------------------------
__global__ void cvt_weights(const float* __restrict__ wcam, const float* __restrict__ wgcn2,
                            const float* __restrict__ wq, const float* __restrict__ wk,
                            const float* __restrict__ wv, const float* __restrict__ wout,
                            __nv_bfloat16* __restrict__ dst)
{
    int i = blockIdx.x * blockDim.x + threadIdx.x;   // 0..1048575
    float v;
    if      (i < 262144)  v = wcam [i];
    else if (i < 524288)  v = wgcn2[i - 262144];
    else if (i < 655360)  v = wq   [i - 524288];
    else if (i < 786432)  v = wk   [i - 655360];
    else if (i < 917504)  v = wv   [i - 786432];
    else                  v = wout [i - 917504];
    dst[i] = __float2bfloat16(v);
}

// ---------------- patch-split transposes -------------------------------------
__global__ void make_xp(const float* __restrict__ x,
                        __nv_bfloat16* __restrict__ xp, __nv_bfloat16* __restrict__ xpt)
{
    __shared__ float t[32][33];
    const int ct = blockIdx.x * 32;
    const int rh = blockIdx.y;
    const int z  = blockIdx.z;            // b*16 + nbin
    const int b  = z >> 4, n = z & 15;
    const int h  = (n >> 2) * 32 + rh;
    const int wb = (n & 3) * 32;
    const int tx = threadIdx.x, ty = threadIdx.y;

    const float* xb = x + ((((long long)b * 512 + ct) * 128 + h) * 128 + wb);
#pragma unroll
    for (int i = 0; i < 4; i++) {
        int cc = ty + 8 * i;
        t[cc][tx] = xb[(long long)cc * 16384 + tx];
    }
    __syncthreads();
    __nv_bfloat16* xpb = xp + (((long long)z * 1024 + rh * 32) * 512) + ct;
#pragma unroll
    for (int i = 0; i < 4; i++) {
        int rw = ty + 8 * i;
        xpb[(long long)rw * 512 + tx] = __float2bfloat16(t[tx][rw]);
    }
    __nv_bfloat16* xptb = xpt + (((long long)z * 512 + ct) * 1024) + rh * 32;
#pragma unroll
    for (int i = 0; i < 4; i++) {
        int cc = ty + 8 * i;
        xptb[(long long)cc * 1024 + tx] = __float2bfloat16(t[cc][tx]);
    }
}

// ---------------- bf16 row softmax (in place), optional sigmoid(mean) -------
template<bool HASCONF>
__global__ void softmax_rows(__nv_bfloat16* __restrict__ data,
                             float* __restrict__ conf, int rowlen)
{
    const int tid = threadIdx.x;
    const long long r = blockIdx.x;
    uint4* row = (uint4*)(data + r * (long long)rowlen);
    uint4 v = row[tid];

    float2 f[4];
    f[0] = __bfloat1622float2(*(__nv_bfloat162*)&v.x);
    f[1] = __bfloat1622float2(*(__nv_bfloat162*)&v.y);
    f[2] = __bfloat1622float2(*(__nv_bfloat162*)&v.z);
    f[3] = __bfloat1622float2(*(__nv_bfloat162*)&v.w);

    float lmax = -3.402823466e38f, lsum = 0.f;
#pragma unroll
    for (int i = 0; i < 4; i++) {
        lmax = fmaxf(lmax, fmaxf(f[i].x, f[i].y));
        lsum += f[i].x + f[i].y;
    }

    __shared__ float sm[32], ss[32];
    const int lane = tid & 31, wid = tid >> 5, nw = blockDim.x >> 5;
    float wmax = warpRedMax(lmax), wsum = warpRedSum(lsum);
    if (lane == 0) { sm[wid] = wmax; ss[wid] = wsum; }
    __syncthreads();
    if (tid < 32) {
        float a  = (tid < nw) ? sm[tid] : -3.402823466e38f;
        float b2 = (tid < nw) ? ss[tid] : 0.f;
        a  = warpRedMax(a);
        b2 = warpRedSum(b2);
        if (tid == 0) { sm[0] = a; ss[0] = b2; }
    }
    __syncthreads();
    const float rmax = sm[0];
    if (HASCONF && tid == 0)
        conf[r] = 1.f / (1.f + expf(-ss[0] / (float)rowlen));
    __syncthreads();

    float les = 0.f;
#pragma unroll
    for (int i = 0; i < 4; i++) {
        f[i].x = expf(f[i].x - rmax);
        f[i].y = expf(f[i].y - rmax);
        les += f[i].x + f[i].y;
    }
    float ws = warpRedSum(les);
    if (lane == 0) ss[wid] = ws;
    __syncthreads();
    if (tid < 32) {
        float b2 = (tid < nw) ? ss[tid] : 0.f;
        b2 = warpRedSum(b2);
        if (tid == 0) ss[0] = b2;
    }
    __syncthreads();
    const float inv = 1.f / ss[0];
    uint4 o;
    __nv_bfloat162 p;
    p = __float22bfloat162_rn(make_float2(f[0].x * inv, f[0].y * inv)); o.x = *(unsigned*)&p;
    p = __float22bfloat162_rn(make_float2(f[1].x * inv, f[1].y * inv)); o.y = *(unsigned*)&p;
    p = __float22bfloat162_rn(make_float2(f[2].x * inv, f[2].y * inv)); o.z = *(unsigned*)&p;
    p = __float22bfloat162_rn(make_float2(f[3].x * inv, f[3].y * inv)); o.w = *(unsigned*)&p;
    row[tid] = o;
}

// ---------------- GCN 16x16 bin mix + residual relu (bf16x2 words) ----------
__global__ void gcn_mix(const __nv_bfloat162* __restrict__ local,
                        const float* __restrict__ w1, __nv_bfloat162* __restrict__ g)
{
    __shared__ float w[256];
    if (threadIdx.x < 256) w[threadIdx.x] = w1[threadIdx.x];
    __syncthreads();
    long long j = (long long)blockIdx.x * blockDim.x + threadIdx.x;
    const int b = (int)(j >> 17);
    const long long jj = j & 131071;
    const __nv_bfloat162* base = local + ((long long)b << 21) + jj;
    float2 v[16];
#pragma unroll
    for (int m = 0; m < 16; m++) v[m] = __bfloat1622float2(base[(long long)m << 17]);
    __nv_bfloat162* ob = g + ((long long)b << 21) + jj;
#pragma unroll
    for (int n = 0; n < 16; n++) {
        float sx = v[n].x, sy = v[n].y;
#pragma unroll
        for (int m = 0; m < 16; m++) {
            sx = fmaf(w[n * 16 + m], v[m].x, sx);
            sy = fmaf(w[n * 16 + m], v[m].y, sy);
        }
        ob[(long long)n << 17] = __float22bfloat162_rn(make_float2(fmaxf(sx, 0.f), fmaxf(sy, 0.f)));
    }
}

// ---------------- fuse: glob = relu(b_fuse + sum_m w_fuse[m]*lf[m]) ----------
__global__ void fuse_glob(const __nv_bfloat162* __restrict__ lf,
                          const float* __restrict__ wf, const float* __restrict__ bf,
                          __nv_bfloat162* __restrict__ glob)
{
    __shared__ float w[16];
    __shared__ float b0;
    if (threadIdx.x < 16) w[threadIdx.x] = wf[threadIdx.x];
    if (threadIdx.x == 16) b0 = bf[0];
    __syncthreads();
    long long j = (long long)blockIdx.x * blockDim.x + threadIdx.x;
    const int b = (int)(j >> 17);
    const long long jj = j & 131071;
    const __nv_bfloat162* base = lf + ((long long)b << 21) + jj;
    float sx = b0, sy = b0;
#pragma unroll
    for (int m = 0; m < 16; m++) {
        float2 v = __bfloat1622float2(base[(long long)m << 17]);
        sx = fmaf(w[m], v.x, sx);
        sy = fmaf(w[m], v.y, sy);
    }
    glob[((long long)b << 17) + jj] =
        __float22bfloat162_rn(make_float2(fmaxf(sx, 0.f), fmaxf(sy, 0.f)));
}

// ---------------- TN GEMM, bf16, ldmatrix + cp.async 3-stage pipeline --------
// C[m,n] = sum_kd A[m,kd]*B[n,kd]. CTA tile 128x128, k-tile 32, 3 stages.
// smem: per stage [128 rows][32 bf16], 16B segs swizzled phys = seg^((row>>1)&3).
// cp.async.cg 16B global->smem (no LDG/STS reg pass); ldmatrix.x4 fragments.
// 8 warps, warp tile 32x64, mma m16n8k16. M,N mult of 128; Kd mult of 32.
__global__ __launch_bounds__(256, 2) void gemm_tn_tc(
    const __nv_bfloat16* __restrict__ Ab, const __nv_bfloat16* __restrict__ Bb,
    __nv_bfloat16* __restrict__ Cb,
    int N, int Kd,
    long long sA, long long sB, long long sC, int zdivB,
    const float* __restrict__ bias, int biasMode,
    const float* __restrict__ rowscale, long long sScale,
    int epi,
    const float* __restrict__ resid, const float* __restrict__ bnS,
    const float* __restrict__ bnT, float* __restrict__ outp)
{
    __shared__ __align__(16) uint4 As[3][512];   // 3 stages x 128 rows x 4 segs
    __shared__ __align__(16) uint4 Bs[3][512];

    const int z = blockIdx.z;
    const __nv_bfloat16* A = Ab + (long long)z * sA;
    const __nv_bfloat16* B = Bb + (long long)(z / zdivB) * sB;

    const int tid  = threadIdx.x;
    const int m0   = blockIdx.y * 128;
    const int n0   = blockIdx.x * 128;

    const int lane = tid & 31;
    const int warp = tid >> 5;
    const int gq   = lane >> 2;
    const int tq   = lane & 3;
    const int m0w  = (warp >> 1) * 32;
    const int n0w  = (warp & 1) * 64;

    // cp.async assignment: row r, k half kq (16 bf16 = 2 segs)
    const int r  = tid >> 1;
    const int kq = tid & 1;
    const int swz = (r >> 1) & 3;
    const int ph0 = (2 * kq)     ^ swz;
    const int ph1 = (2 * kq + 1) ^ swz;
    const __nv_bfloat16* Ag = A + (long long)(m0 + r) * Kd + kq * 16;
    const __nv_bfloat16* Bg = B + (long long)(n0 + r) * Kd + kq * 16;

    const unsigned aBase = (unsigned)__cvta_generic_to_shared(As);
    const unsigned bBase = (unsigned)__cvta_generic_to_shared(Bs);
    const unsigned sOffA0 = (unsigned)((r * 4 + ph0) << 4);
    const unsigned sOffA1 = (unsigned)((r * 4 + ph1) << 4);

    // ldmatrix lane addressing
    const int mi  = lane >> 3;
    const int wr  = lane & 7;
    const int lrow = (mi & 1) * 8 + wr;
    const int segS = mi >> 1;

    float acc[2][8][4];
#pragma unroll
    for (int i = 0; i < 2; i++)
#pragma unroll
        for (int j = 0; j < 8; j++)
#pragma unroll
            for (int q = 0; q < 4; q++) acc[i][j][q] = 0.f;

    const int T = Kd >> 5;

    // pipeline issue helper (stage = it % 3)
    auto issue = [&](int it){
        const int s = it - (it / 3) * 3;
        const unsigned sb = (unsigned)(s * 8192);   // 512 uint4 = 8192 B
        const __nv_bfloat16* ag = Ag + it * 32;
        const __nv_bfloat16* bg = Bg + it * 32;
        cp16(aBase + sb + sOffA0, ag);
        cp16(aBase + sb + sOffA1, ag + 8);
        cp16(bBase + sb + sOffA0, bg);
        cp16(bBase + sb + sOffA1, bg + 8);
        asm volatile("cp.async.commit_group;" ::: "memory");
    };

    issue(0);
    issue(1);

    for (int it = 0; it < T; it++) {
        const int s = it - (it / 3) * 3;
        asm volatile("cp.async.wait_group 1;" ::: "memory");
        __syncthreads();
        if (it + 2 < T) issue(it + 2);

#pragma unroll
        for (int kk = 0; kk < 2; kk++) {
            const int seg = 2 * kk + segS;
            unsigned af[2][4], bf[8][2];
#pragma unroll
            for (int mt = 0; mt < 2; mt++) {
                const int row = m0w + mt * 16 + lrow;
                const int phys = seg ^ ((row >> 1) & 3);
                ldsm_x4(af[mt][0], af[mt][1], af[mt][2], af[mt][3],
                        aBase + (unsigned)((s * 512 + row * 4 + phys) << 4));
            }
#pragma unroll
            for (int nt2 = 0; nt2 < 4; nt2++) {
                const int row = n0w + nt2 * 16 + lrow;
                const int phys = seg ^ ((row >> 1) & 3);
                unsigned t0, t1, t2, t3;
                ldsm_x4(t0, t1, t2, t3,
                        bBase + (unsigned)((s * 512 + row * 4 + phys) << 4));
                bf[2 * nt2][0] = t0; bf[2 * nt2 + 1][0] = t1;
                bf[2 * nt2][1] = t2; bf[2 * nt2 + 1][1] = t3;
            }
#pragma unroll
            for (int mt = 0; mt < 2; mt++)
#pragma unroll
                for (int nt = 0; nt < 8; nt++)
                    mma_bf16(acc[mt][nt], af[mt], bf[nt]);
        }
    }

    // ---- epilogue ----
    // element (mt,h,nt,q): row = m0+m0w+mt*16+gq+h*8 ; col = n0+n0w+nt*8+2*tq+q
    if (biasMode == 1) {
#pragma unroll
        for (int mt = 0; mt < 2; mt++)
#pragma unroll
            for (int h = 0; h < 2; h++) {
                const float bb = bias[m0 + m0w + mt * 16 + gq + h * 8];
#pragma unroll
                for (int nt = 0; nt < 8; nt++) {
                    acc[mt][nt][h * 2 + 0] += bb;
                    acc[mt][nt][h * 2 + 1] += bb;
                }
            }
    } else if (biasMode == 2) {
#pragma unroll
        for (int nt = 0; nt < 8; nt++) {
            const int c0 = n0 + n0w + nt * 8 + 2 * tq;
            const float b0v = bias[c0], b1v = bias[c0 + 1];
#pragma unroll
            for (int mt = 0; mt < 2; mt++) {
                acc[mt][nt][0] += b0v; acc[mt][nt][1] += b1v;
                acc[mt][nt][2] += b0v; acc[mt][nt][3] += b1v;
            }
        }
    }
    if (rowscale) {
        const float* rs = rowscale + (long long)z * sScale;
#pragma unroll
        for (int mt = 0; mt < 2; mt++)
#pragma unroll
            for (int h = 0; h < 2; h++) {
                const float f = rs[m0 + m0w + mt * 16 + gq + h * 8];
#pragma unroll
                for (int nt = 0; nt < 8; nt++) {
                    acc[mt][nt][h * 2 + 0] *= f;
                    acc[mt][nt][h * 2 + 1] *= f;
                }
            }
    }

    if (epi == 0) {
        __nv_bfloat16* C = Cb + (long long)z * sC;
#pragma unroll
        for (int mt = 0; mt < 2; mt++)
#pragma unroll
            for (int h = 0; h < 2; h++) {
                const int row = m0 + m0w + mt * 16 + gq + h * 8;
                __nv_bfloat16* cp = C + (long long)row * N + n0 + n0w + 2 * tq;
#pragma unroll
                for (int nt = 0; nt < 8; nt++)
                    *(__nv_bfloat162*)(cp + nt * 8) =
                        __float22bfloat162_rn(
                            make_float2(acc[mt][nt][h * 2 + 0], acc[mt][nt][h * 2 + 1]));
            }
    } else {
        const int b = z >> 4, nbin = z & 15;
        const int hb = (nbin >> 2) * 32, wb = (nbin & 3) * 32;
#pragma unroll
        for (int mt = 0; mt < 2; mt++)
#pragma unroll
            for (int h2 = 0; h2 < 2; h2++) {
                const int co = m0 + m0w + mt * 16 + gq + h2 * 8;
                const float sc = bnS[co], tt = bnT[co];
                const long long cbase = ((long long)(b * 512 + co) * 128);
#pragma unroll
                for (int nt = 0; nt < 8; nt++) {
                    const int p = n0 + n0w + nt * 8 + 2 * tq;   // even
                    const int hh = hb + (p >> 5);
                    const int ww = wb + (p & 31);
                    const long long oi = (cbase + hh) * 128 + ww;
                    float2 rv = *(const float2*)(resid + oi);
                    float v0 = fmaxf(fmaf(acc[mt][nt][h2 * 2 + 0], sc, tt), 0.f);
                    float v1 = fmaxf(fmaf(acc[mt][nt][h2 * 2 + 1], sc, tt), 0.f);
                    *(float2*)(outp + oi) = make_float2(rv.x + v0, rv.y + v1);
                }
            }
    }
}

// ---------------- host side --------------------------------------------------
static void gemm(const __nv_bfloat16* A, const __nv_bfloat16* B, __nv_bfloat16* C,
                 int M, int N, int Kd,
                 long long sA, long long sB, long long sC, int Z, int zdivB = 1,
                 const float* bias = nullptr, int biasMode = 0,
                 const float* rowscale = nullptr, long long sScale = 0,
                 int epi = 0, const float* resid = nullptr,
                 const float* bnS = nullptr, const float* bnT = nullptr,
                 float* outp = nullptr)
{
    dim3 grid(N / 128, M / 128, Z), block(256);
    gemm_tn_tc<<<grid, block>>>(A, B, C, N, Kd, sA, sB, sC, zdivB,
                                bias, biasMode, rowscale, sScale,
                                epi, resid, bnS, bnT, outp);
}

extern "C" void kernel_launch(void* const* d_in, const int* in_sizes, int n_in,
                              void* d_out, int out_size)
{
    const float* x      = (const float*)d_in[0];
    const float* w_cam  = (const float*)d_in[1];
    const float* b_cam  = (const float*)d_in[2];
    const float* w_gcn1 = (const float*)d_in[3];
    const float* w_gcn2 = (const float*)d_in[4];
    const float* w_fuse = (const float*)d_in[5];
    const float* b_fuse = (const float*)d_in[6];
    const float* w_q    = (const float*)d_in[7];
    const float* b_q    = (const float*)d_in[8];
    const float* w_k    = (const float*)d_in[9];
    const float* b_k    = (const float*)d_in[10];
    const float* w_v    = (const float*)d_in[11];
    const float* b_v    = (const float*)d_in[12];
    const float* w_out  = (const float*)d_in[13];
    const float* bn_g   = (const float*)d_in[14];
    const float* bn_b   = (const float*)d_in[15];
    const float* bn_m   = (const float*)d_in[16];
    const float* bn_v   = (const float*)d_in[17];
    float* out = (float*)d_out;

    __nv_bfloat16 *xp, *xpt, *cam, *aff, *loc, *gg, *lf, *qry, *oat, *key, *glob, *valT, *wbf;
    float *bconf, *bnS, *bnT;
    cudaGetSymbolAddress((void**)&xp,    g_xp);
    cudaGetSymbolAddress((void**)&xpt,   g_xpt);
    cudaGetSymbolAddress((void**)&cam,   g_cam);
    cudaGetSymbolAddress((void**)&aff,   g_aff);
    cudaGetSymbolAddress((void**)&loc,   g_local);
    cudaGetSymbolAddress((void**)&gg,    g_g);
    cudaGetSymbolAddress((void**)&lf,    g_lf);
    cudaGetSymbolAddress((void**)&qry,   g_query);
    cudaGetSymbolAddress((void**)&oat,   g_oattn);
    cudaGetSymbolAddress((void**)&key,   g_key);
    cudaGetSymbolAddress((void**)&glob,  g_glob);
    cudaGetSymbolAddress((void**)&valT,  g_valT);
    cudaGetSymbolAddress((void**)&wbf,   g_wbf);
    cudaGetSymbolAddress((void**)&bconf, g_bconf);
    cudaGetSymbolAddress((void**)&bnS,   g_bnS);
    cudaGetSymbolAddress((void**)&bnT,   g_bnT);

    // constants
    prep_bn<<<1, 512>>>(bn_g, bn_b, bn_m, bn_v, bnS, bnT);
    cvt_weights<<<4096, 256>>>(w_cam, w_gcn2, w_q, w_k, w_v, w_out, wbf);

    // patch-split transposes (fp32 -> bf16)
    make_xp<<<dim3(16, 32, 64), dim3(32, 8)>>>(x, xp, xpt);

    // cam^T[b,n,k,p] = w_cam @ x_p^T (+b_cam per row k)
    gemm(wbf + W_CAM, xp, cam, 512, 1024, 512, 0, 524288, 524288, 64, 1, b_cam, 1);

    // pixel softmax over p + bin_conf = sigmoid(row mean)
    softmax_rows<true><<<32768, 128>>>(cam, bconf, 1024);

    // local[b,n,k,c] = (conf^T @ x_p) * bin_conf[k]
    gemm(cam, xpt, loc, 512, 512, 1024, 524288, 524288, 262144, 64, 1,
         nullptr, 0, bconf, 512);

    // GCN bin mix + residual relu
    gcn_mix<<<2048, 256>>>((const __nv_bfloat162*)loc, w_gcn1, (__nv_bfloat162*)gg);

    // local_feats = g @ w_gcn2^T
    gemm(gg, wbf + W_GCN2, lf, 32768, 512, 512, 0, 0, 0, 1);

    // glob = relu(fuse over bins + b_fuse)
    fuse_glob<<<2048, 256>>>((const __nv_bfloat162*)lf, w_fuse, b_fuse,
                             (__nv_bfloat162*)glob);

    // query / key / value^T
    gemm(xp, wbf + W_Q, qry, 65536, 256, 512, 0, 0, 0, 1, 1, b_q, 2);
    gemm(lf, wbf + W_K, key, 32768, 256, 512, 0, 0, 0, 1, 1, b_k, 2);
    gemm(wbf + W_V, glob, valT, 256, 512, 512, 0, 262144, 131072, 4, 1, b_v, 1);

    // aff = query @ key^T per (b,bin); softmax over k
    gemm(qry, key, aff, 1024, 512, 256, 262144, 131072, 524288, 64);
    softmax_rows<false><<<65536, 64>>>(aff, nullptr, 512);

    // out_attn = aff @ value (value shared across bins: zdivB=16)
    gemm(aff, valT, oat, 1024, 256, 512, 524288, 131072, 262144, 64, 16);

    // final 1x1 conv + BN + relu + residual, patch-recover fused epilogue
    gemm(wbf + W_OUT, oat, nullptr, 512, 1024, 256, 0, 262144, 0, 64, 1,
         nullptr, 0, nullptr, 0, 2, x, bnS, bnT, out);
}

// round 9
// speedup vs baseline: 5.3578x; 1.0800x over previous
#include <cuda_runtime.h>
#include <cuda_bf16.h>
#include <math.h>

// ---------------- scratch (device globals; no allocations allowed) ----------
__device__ unsigned short g_xp   [33554432];   // [B,16,1024,512]
__device__ unsigned short g_xpt  [33554432];   // [B,16,512,1024]
__device__ unsigned short g_cam  [33554432];   // [B,16,512,1024] logits -> conf
__device__ unsigned short g_aff  [33554432];   // [B,16,1024,512]
__device__ unsigned short g_local[16777216];   // [B,16,512,512]
__device__ unsigned short g_g    [16777216];
__device__ unsigned short g_lf   [16777216];
__device__ unsigned short g_query[16777216];   // [B,16,1024,256]
__device__ unsigned short g_oattn[16777216];   // [B,16,1024,256]
__device__ unsigned short g_key  [ 8388608];   // [B,16,512,256]
__device__ unsigned short g_glob [ 1048576];   // [B,512,512]
__device__ unsigned short g_valT [  524288];   // [B,256,512]
__device__ unsigned short g_wbf  [ 1048576];   // packed bf16 weights
__device__ float g_bconf[32768];
__device__ float g_bnS  [512];
__device__ float g_bnT  [512];

#define W_CAM  0
#define W_GCN2 262144
#define W_Q    524288
#define W_K    655360
#define W_V    786432
#define W_OUT  917504

// ---------------- small helpers --------------------------------------------
__device__ __forceinline__ float warpRedSum(float v){
#pragma unroll
    for (int o = 16; o; o >>= 1) v += __shfl_xor_sync(0xffffffffu, v, o);
    return v;
}
__device__ __forceinline__ float warpRedMax(float v){
#pragma unroll
    for (int o = 16; o; o >>= 1) v = fmaxf(v, __shfl_xor_sync(0xffffffffu, v, o));
    return v;
}
__device__ __forceinline__ void mma_bf16(float* d, const unsigned* a, const unsigned* b){
    asm volatile(
        "mma.sync.aligned.m16n8k16.row.col.f32.bf16.bf16.f32 "
        "{%0,%1,%2,%3}, {%4,%5,%6,%7}, {%8,%9}, {%0,%1,%2,%3};"
        : "+f"(d[0]), "+f"(d[1]), "+f"(d[2]), "+f"(d[3])
        : "r"(a[0]), "r"(a[1]), "r"(a[2]), "r"(a[3]), "r"(b[0]), "r"(b[1]));
}
__device__ __forceinline__ void ldsm_x4(unsigned& r0, unsigned& r1,
                                        unsigned& r2, unsigned& r3, unsigned addr){
    asm volatile("ldmatrix.sync.aligned.m8n8.x4.shared.b16 {%0,%1,%2,%3}, [%4];"
                 : "=r"(r0), "=r"(r1), "=r"(r2), "=r"(r3) : "r"(addr));
}
__device__ __forceinline__ void cp16(unsigned saddr, const void* gptr){
    asm volatile("cp.async.cg.shared.global [%0], [%1], 16;"
                 :: "r"(saddr), "l"(gptr) : "memory");
}

// ---------------- BN constant prep ------------------------------------------
__global__ void prep_bn(const float* __restrict__ gam, const float* __restrict__ bet,
                        const float* __restrict__ mean, const float* __restrict__ var,
                        float* __restrict__ S, float* __restrict__ T)
{
    int i = threadIdx.x;
    if (i < 512) {
        float inv = rsqrtf(var[i] + 1e-5f);
        float s = gam[i] * inv;
        S[i] = s;
        T[i] = bet[i] - mean[i] * s;
    }
}

// ---------------- weights fp32 -> bf16 ---------------------------------------
__global__ void cvt_weights(const float* __restrict__ wcam, const float* __restrict__ wgcn2,
                            const float* __restrict__ wq, const float* __restrict__ wk,
                            const float* __restrict__ wv, const float* __restrict__ wout,
                            __nv_bfloat16* __restrict__ dst)
{
    int i = blockIdx.x * blockDim.x + threadIdx.x;   // 0..1048575
    float v;
    if      (i < 262144)  v = wcam [i];
    else if (i < 524288)  v = wgcn2[i - 262144];
    else if (i < 655360)  v = wq   [i - 524288];
    else if (i < 786432)  v = wk   [i - 655360];
    else if (i < 917504)  v = wv   [i - 786432];
    else                  v = wout [i - 917504];
    dst[i] = __float2bfloat16(v);
}

// ---------------- patch-split transposes -------------------------------------
__global__ void make_xp(const float* __restrict__ x,
                        __nv_bfloat16* __restrict__ xp, __nv_bfloat16* __restrict__ xpt)
{
    __shared__ float t[32][33];
    const int ct = blockIdx.x * 32;
    const int rh = blockIdx.y;
    const int z  = blockIdx.z;            // b*16 + nbin
    const int b  = z >> 4, n = z & 15;
    const int h  = (n >> 2) * 32 + rh;
    const int wb = (n & 3) * 32;
    const int tx = threadIdx.x, ty = threadIdx.y;

    const float* xb = x + ((((long long)b * 512 + ct) * 128 + h) * 128 + wb);
#pragma unroll
    for (int i = 0; i < 4; i++) {
        int cc = ty + 8 * i;
        t[cc][tx] = xb[(long long)cc * 16384 + tx];
    }
    __syncthreads();
    __nv_bfloat16* xpb = xp + (((long long)z * 1024 + rh * 32) * 512) + ct;
#pragma unroll
    for (int i = 0; i < 4; i++) {
        int rw = ty + 8 * i;
        xpb[(long long)rw * 512 + tx] = __float2bfloat16(t[tx][rw]);
    }
    __nv_bfloat16* xptb = xpt + (((long long)z * 512 + ct) * 1024) + rh * 32;
#pragma unroll
    for (int i = 0; i < 4; i++) {
        int cc = ty + 8 * i;
        xptb[(long long)cc * 1024 + tx] = __float2bfloat16(t[cc][tx]);
    }
}

// ---------------- bf16 row softmax (in place), optional sigmoid(mean) -------
template<bool HASCONF>
__global__ void softmax_rows(__nv_bfloat16* __restrict__ data,
                             float* __restrict__ conf, int rowlen)
{
    const int tid = threadIdx.x;
    const long long r = blockIdx.x;
    uint4* row = (uint4*)(data + r * (long long)rowlen);
    uint4 v = row[tid];

    float2 f[4];
    f[0] = __bfloat1622float2(*(__nv_bfloat162*)&v.x);
    f[1] = __bfloat1622float2(*(__nv_bfloat162*)&v.y);
    f[2] = __bfloat1622float2(*(__nv_bfloat162*)&v.z);
    f[3] = __bfloat1622float2(*(__nv_bfloat162*)&v.w);

    float lmax = -3.402823466e38f, lsum = 0.f;
#pragma unroll
    for (int i = 0; i < 4; i++) {
        lmax = fmaxf(lmax, fmaxf(f[i].x, f[i].y));
        lsum += f[i].x + f[i].y;
    }

    __shared__ float sm[32], ss[32];
    const int lane = tid & 31, wid = tid >> 5, nw = blockDim.x >> 5;
    float wmax = warpRedMax(lmax), wsum = warpRedSum(lsum);
    if (lane == 0) { sm[wid] = wmax; ss[wid] = wsum; }
    __syncthreads();
    if (tid < 32) {
        float a  = (tid < nw) ? sm[tid] : -3.402823466e38f;
        float b2 = (tid < nw) ? ss[tid] : 0.f;
        a  = warpRedMax(a);
        b2 = warpRedSum(b2);
        if (tid == 0) { sm[0] = a; ss[0] = b2; }
    }
    __syncthreads();
    const float rmax = sm[0];
    if (HASCONF && tid == 0)
        conf[r] = 1.f / (1.f + expf(-ss[0] / (float)rowlen));
    __syncthreads();

    float les = 0.f;
#pragma unroll
    for (int i = 0; i < 4; i++) {
        f[i].x = expf(f[i].x - rmax);
        f[i].y = expf(f[i].y - rmax);
        les += f[i].x + f[i].y;
    }
    float ws = warpRedSum(les);
    if (lane == 0) ss[wid] = ws;
    __syncthreads();
    if (tid < 32) {
        float b2 = (tid < nw) ? ss[tid] : 0.f;
        b2 = warpRedSum(b2);
        if (tid == 0) ss[0] = b2;
    }
    __syncthreads();
    const float inv = 1.f / ss[0];
    uint4 o;
    __nv_bfloat162 p;
    p = __float22bfloat162_rn(make_float2(f[0].x * inv, f[0].y * inv)); o.x = *(unsigned*)&p;
    p = __float22bfloat162_rn(make_float2(f[1].x * inv, f[1].y * inv)); o.y = *(unsigned*)&p;
    p = __float22bfloat162_rn(make_float2(f[2].x * inv, f[2].y * inv)); o.z = *(unsigned*)&p;
    p = __float22bfloat162_rn(make_float2(f[3].x * inv, f[3].y * inv)); o.w = *(unsigned*)&p;
    row[tid] = o;
}

// ---------------- GCN 16x16 bin mix + residual relu (bf16x2 words) ----------
__global__ void gcn_mix(const __nv_bfloat162* __restrict__ local,
                        const float* __restrict__ w1, __nv_bfloat162* __restrict__ g)
{
    __shared__ float w[256];
    if (threadIdx.x < 256) w[threadIdx.x] = w1[threadIdx.x];
    __syncthreads();
    long long j = (long long)blockIdx.x * blockDim.x + threadIdx.x;
    const int b = (int)(j >> 17);
    const long long jj = j & 131071;
    const __nv_bfloat162* base = local + ((long long)b << 21) + jj;
    float2 v[16];
#pragma unroll
    for (int m = 0; m < 16; m++) v[m] = __bfloat1622float2(base[(long long)m << 17]);
    __nv_bfloat162* ob = g + ((long long)b << 21) + jj;
#pragma unroll
    for (int n = 0; n < 16; n++) {
        float sx = v[n].x, sy = v[n].y;
#pragma unroll
        for (int m = 0; m < 16; m++) {
            sx = fmaf(w[n * 16 + m], v[m].x, sx);
            sy = fmaf(w[n * 16 + m], v[m].y, sy);
        }
        ob[(long long)n << 17] = __float22bfloat162_rn(make_float2(fmaxf(sx, 0.f), fmaxf(sy, 0.f)));
    }
}

// ---------------- fuse: glob = relu(b_fuse + sum_m w_fuse[m]*lf[m]) ----------
__global__ void fuse_glob(const __nv_bfloat162* __restrict__ lf,
                          const float* __restrict__ wf, const float* __restrict__ bf,
                          __nv_bfloat162* __restrict__ glob)
{
    __shared__ float w[16];
    __shared__ float b0;
    if (threadIdx.x < 16) w[threadIdx.x] = wf[threadIdx.x];
    if (threadIdx.x == 16) b0 = bf[0];
    __syncthreads();
    long long j = (long long)blockIdx.x * blockDim.x + threadIdx.x;
    const int b = (int)(j >> 17);
    const long long jj = j & 131071;
    const __nv_bfloat162* base = lf + ((long long)b << 21) + jj;
    float sx = b0, sy = b0;
#pragma unroll
    for (int m = 0; m < 16; m++) {
        float2 v = __bfloat1622float2(base[(long long)m << 17]);
        sx = fmaf(w[m], v.x, sx);
        sy = fmaf(w[m], v.y, sy);
    }
    glob[((long long)b << 17) + jj] =
        __float22bfloat162_rn(make_float2(fmaxf(sx, 0.f), fmaxf(sy, 0.f)));
}

// ---------------- TN GEMM, bf16, ldmatrix + cp.async 4-stage pipeline --------
// C[m,n] = sum_kd A[m,kd]*B[n,kd]. CTA tile 128x128, k-tile 32, 4 stages
// (dynamic smem 64KB, 2 CTAs/SM). Uniform commit_group every iteration so
// wait_group 2 always proves stage `it` landed (no tail race).
// ldmatrix addresses precomputed per warp; inner loop adds stage offset only.
__global__ __launch_bounds__(256, 2) void gemm_tn_tc(
    const __nv_bfloat16* __restrict__ Ab, const __nv_bfloat16* __restrict__ Bb,
    __nv_bfloat16* __restrict__ Cb,
    int N, int Kd,
    long long sA, long long sB, long long sC, int zdivB,
    const float* __restrict__ bias, int biasMode,
    const float* __restrict__ rowscale, long long sScale,
    int epi,
    const float* __restrict__ resid, const float* __restrict__ bnS,
    const float* __restrict__ bnT, float* __restrict__ outp)
{
    extern __shared__ __align__(16) char dsm[];
    // A stages: bytes [0, 32768), B stages: [32768, 65536); stage stride 8192.
    const unsigned aBase = (unsigned)__cvta_generic_to_shared(dsm);
    const unsigned bBase = aBase + 32768;

    const int z = blockIdx.z;
    const __nv_bfloat16* A = Ab + (long long)z * sA;
    const __nv_bfloat16* B = Bb + (long long)(z / zdivB) * sB;

    const int tid  = threadIdx.x;
    const int m0   = blockIdx.y * 128;
    const int n0   = blockIdx.x * 128;

    const int lane = tid & 31;
    const int warp = tid >> 5;
    const int gq   = lane >> 2;
    const int tq   = lane & 3;
    const int m0w  = (warp >> 1) * 32;
    const int n0w  = (warp & 1) * 64;

    // cp.async assignment: row r, k half kq (16 bf16 = 2 segs)
    const int r  = tid >> 1;
    const int kq = tid & 1;
    const int swz = (r >> 1) & 3;
    const int ph0 = (2 * kq)     ^ swz;
    const int ph1 = (2 * kq + 1) ^ swz;
    const __nv_bfloat16* Ag = A + (long long)(m0 + r) * Kd + kq * 16;
    const __nv_bfloat16* Bg = B + (long long)(n0 + r) * Kd + kq * 16;
    const unsigned sOffA0 = (unsigned)((r * 4 + ph0) << 4);
    const unsigned sOffA1 = (unsigned)((r * 4 + ph1) << 4);

    // ldmatrix lane addressing
    const int mi  = lane >> 3;
    const int wr  = lane & 7;
    const int lrow = (mi & 1) * 8 + wr;
    const int segS = mi >> 1;

    const int T = Kd >> 5;

    auto issue = [&](int it){
        if (it < T) {
            const unsigned sb = (unsigned)((it & 3) * 8192);
            const __nv_bfloat16* ag = Ag + it * 32;
            const __nv_bfloat16* bg = Bg + it * 32;
            cp16(aBase + sb + sOffA0, ag);
            cp16(aBase + sb + sOffA1, ag + 8);
            cp16(bBase + sb + sOffA0, bg);
            cp16(bBase + sb + sOffA1, bg + 8);
        }
        asm volatile("cp.async.commit_group;" ::: "memory");
    };

    issue(0); issue(1); issue(2);

    // precomputed ldmatrix addresses (stage 0); inner loop adds stage offset
    unsigned aAd[2][2], bAd[2][4];
#pragma unroll
    for (int kk = 0; kk < 2; kk++) {
#pragma unroll
        for (int mt = 0; mt < 2; mt++) {
            const int row = m0w + mt * 16 + lrow;
            const int phys = (2 * kk + segS) ^ ((row >> 1) & 3);
            aAd[kk][mt] = aBase + (unsigned)((row * 4 + phys) << 4);
        }
#pragma unroll
        for (int nt2 = 0; nt2 < 4; nt2++) {
            const int row = n0w + nt2 * 16 + lrow;
            const int phys = (2 * kk + segS) ^ ((row >> 1) & 3);
            bAd[kk][nt2] = bBase + (unsigned)((row * 4 + phys) << 4);
        }
    }

    float acc[2][8][4];
#pragma unroll
    for (int i = 0; i < 2; i++)
#pragma unroll
        for (int j = 0; j < 8; j++)
#pragma unroll
            for (int q = 0; q < 4; q++) acc[i][j][q] = 0.f;

    for (int it = 0; it < T; it++) {
        asm volatile("cp.async.wait_group 2;" ::: "memory");
        __syncthreads();
        issue(it + 3);
        const unsigned sb = (unsigned)((it & 3) * 8192);

#pragma unroll
        for (int kk = 0; kk < 2; kk++) {
            unsigned af[2][4], bf[8][2];
#pragma unroll
            for (int mt = 0; mt < 2; mt++)
                ldsm_x4(af[mt][0], af[mt][1], af[mt][2], af[mt][3],
                        aAd[kk][mt] + sb);
#pragma unroll
            for (int nt2 = 0; nt2 < 4; nt2++) {
                unsigned t0, t1, t2, t3;
                ldsm_x4(t0, t1, t2, t3, bAd[kk][nt2] + sb);
                bf[2 * nt2][0] = t0; bf[2 * nt2 + 1][0] = t1;
                bf[2 * nt2][1] = t2; bf[2 * nt2 + 1][1] = t3;
            }
#pragma unroll
            for (int mt = 0; mt < 2; mt++)
#pragma unroll
                for (int nt = 0; nt < 8; nt++)
                    mma_bf16(acc[mt][nt], af[mt], bf[nt]);
        }
    }

    // ---- epilogue ----
    // element (mt,h,nt,q): row = m0+m0w+mt*16+gq+h*8 ; col = n0+n0w+nt*8+2*tq+q
    if (biasMode == 1) {
#pragma unroll
        for (int mt = 0; mt < 2; mt++)
#pragma unroll
            for (int h = 0; h < 2; h++) {
                const float bb = bias[m0 + m0w + mt * 16 + gq + h * 8];
#pragma unroll
                for (int nt = 0; nt < 8; nt++) {
                    acc[mt][nt][h * 2 + 0] += bb;
                    acc[mt][nt][h * 2 + 1] += bb;
                }
            }
    } else if (biasMode == 2) {
#pragma unroll
        for (int nt = 0; nt < 8; nt++) {
            const int c0 = n0 + n0w + nt * 8 + 2 * tq;
            const float b0v = bias[c0], b1v = bias[c0 + 1];
#pragma unroll
            for (int mt = 0; mt < 2; mt++) {
                acc[mt][nt][0] += b0v; acc[mt][nt][1] += b1v;
                acc[mt][nt][2] += b0v; acc[mt][nt][3] += b1v;
            }
        }
    }
    if (rowscale) {
        const float* rs = rowscale + (long long)z * sScale;
#pragma unroll
        for (int mt = 0; mt < 2; mt++)
#pragma unroll
            for (int h = 0; h < 2; h++) {
                const float f = rs[m0 + m0w + mt * 16 + gq + h * 8];
#pragma unroll
                for (int nt = 0; nt < 8; nt++) {
                    acc[mt][nt][h * 2 + 0] *= f;
                    acc[mt][nt][h * 2 + 1] *= f;
                }
            }
    }

    if (epi == 0) {
        __nv_bfloat16* C = Cb + (long long)z * sC;
#pragma unroll
        for (int mt = 0; mt < 2; mt++)
#pragma unroll
            for (int h = 0; h < 2; h++) {
                const int row = m0 + m0w + mt * 16 + gq + h * 8;
                __nv_bfloat16* cp = C + (long long)row * N + n0 + n0w + 2 * tq;
#pragma unroll
                for (int nt = 0; nt < 8; nt++)
                    *(__nv_bfloat162*)(cp + nt * 8) =
                        __float22bfloat162_rn(
                            make_float2(acc[mt][nt][h * 2 + 0], acc[mt][nt][h * 2 + 1]));
            }
    } else {
        const int b = z >> 4, nbin = z & 15;
        const int hb = (nbin >> 2) * 32, wb = (nbin & 3) * 32;
#pragma unroll
        for (int mt = 0; mt < 2; mt++)
#pragma unroll
            for (int h2 = 0; h2 < 2; h2++) {
                const int co = m0 + m0w + mt * 16 + gq + h2 * 8;
                const float sc = bnS[co], tt = bnT[co];
                const long long cbase = ((long long)(b * 512 + co) * 128);
#pragma unroll
                for (int nt = 0; nt < 8; nt++) {
                    const int p = n0 + n0w + nt * 8 + 2 * tq;   // even
                    const int hh = hb + (p >> 5);
                    const int ww = wb + (p & 31);
                    const long long oi = (cbase + hh) * 128 + ww;
                    float2 rv = *(const float2*)(resid + oi);
                    float v0 = fmaxf(fmaf(acc[mt][nt][h2 * 2 + 0], sc, tt), 0.f);
                    float v1 = fmaxf(fmaf(acc[mt][nt][h2 * 2 + 1], sc, tt), 0.f);
                    *(float2*)(outp + oi) = make_float2(rv.x + v0, rv.y + v1);
                }
            }
    }
}

// ---------------- host side --------------------------------------------------
#define GEMM_SMEM 65536

static void gemm(const __nv_bfloat16* A, const __nv_bfloat16* B, __nv_bfloat16* C,
                 int M, int N, int Kd,
                 long long sA, long long sB, long long sC, int Z, int zdivB = 1,
                 const float* bias = nullptr, int biasMode = 0,
                 const float* rowscale = nullptr, long long sScale = 0,
                 int epi = 0, const float* resid = nullptr,
                 const float* bnS = nullptr, const float* bnT = nullptr,
                 float* outp = nullptr)
{
    dim3 grid(N / 128, M / 128, Z), block(256);
    gemm_tn_tc<<<grid, block, GEMM_SMEM>>>(A, B, C, N, Kd, sA, sB, sC, zdivB,
                                           bias, biasMode, rowscale, sScale,
                                           epi, resid, bnS, bnT, outp);
}

extern "C" void kernel_launch(void* const* d_in, const int* in_sizes, int n_in,
                              void* d_out, int out_size)
{
    const float* x      = (const float*)d_in[0];
    const float* w_cam  = (const float*)d_in[1];
    const float* b_cam  = (const float*)d_in[2];
    const float* w_gcn1 = (const float*)d_in[3];
    const float* w_gcn2 = (const float*)d_in[4];
    const float* w_fuse = (const float*)d_in[5];
    const float* b_fuse = (const float*)d_in[6];
    const float* w_q    = (const float*)d_in[7];
    const float* b_q    = (const float*)d_in[8];
    const float* w_k    = (const float*)d_in[9];
    const float* b_k    = (const float*)d_in[10];
    const float* w_v    = (const float*)d_in[11];
    const float* b_v    = (const float*)d_in[12];
    const float* w_out  = (const float*)d_in[13];
    const float* bn_g   = (const float*)d_in[14];
    const float* bn_b   = (const float*)d_in[15];
    const float* bn_m   = (const float*)d_in[16];
    const float* bn_v   = (const float*)d_in[17];
    float* out = (float*)d_out;

    // opt-in to 64KB dynamic smem (host attribute set; not a stream op)
    cudaFuncSetAttribute(gemm_tn_tc, cudaFuncAttributeMaxDynamicSharedMemorySize,
                         GEMM_SMEM);

    __nv_bfloat16 *xp, *xpt, *cam, *aff, *loc, *gg, *lf, *qry, *oat, *key, *glob, *valT, *wbf;
    float *bconf, *bnS, *bnT;
    cudaGetSymbolAddress((void**)&xp,    g_xp);
    cudaGetSymbolAddress((void**)&xpt,   g_xpt);
    cudaGetSymbolAddress((void**)&cam,   g_cam);
    cudaGetSymbolAddress((void**)&aff,   g_aff);
    cudaGetSymbolAddress((void**)&loc,   g_local);
    cudaGetSymbolAddress((void**)&gg,    g_g);
    cudaGetSymbolAddress((void**)&lf,    g_lf);
    cudaGetSymbolAddress((void**)&qry,   g_query);
    cudaGetSymbolAddress((void**)&oat,   g_oattn);
    cudaGetSymbolAddress((void**)&key,   g_key);
    cudaGetSymbolAddress((void**)&glob,  g_glob);
    cudaGetSymbolAddress((void**)&valT,  g_valT);
    cudaGetSymbolAddress((void**)&wbf,   g_wbf);
    cudaGetSymbolAddress((void**)&bconf, g_bconf);
    cudaGetSymbolAddress((void**)&bnS,   g_bnS);
    cudaGetSymbolAddress((void**)&bnT,   g_bnT);

    // constants
    prep_bn<<<1, 512>>>(bn_g, bn_b, bn_m, bn_v, bnS, bnT);
    cvt_weights<<<4096, 256>>>(w_cam, w_gcn2, w_q, w_k, w_v, w_out, wbf);

    // patch-split transposes (fp32 -> bf16)
    make_xp<<<dim3(16, 32, 64), dim3(32, 8)>>>(x, xp, xpt);

    // cam^T[b,n,k,p] = w_cam @ x_p^T (+b_cam per row k)
    gemm(wbf + W_CAM, xp, cam, 512, 1024, 512, 0, 524288, 524288, 64, 1, b_cam, 1);

    // pixel softmax over p + bin_conf = sigmoid(row mean)
    softmax_rows<true><<<32768, 128>>>(cam, bconf, 1024);

    // local[b,n,k,c] = (conf^T @ x_p) * bin_conf[k]
    gemm(cam, xpt, loc, 512, 512, 1024, 524288, 524288, 262144, 64, 1,
         nullptr, 0, bconf, 512);

    // GCN bin mix + residual relu
    gcn_mix<<<2048, 256>>>((const __nv_bfloat162*)loc, w_gcn1, (__nv_bfloat162*)gg);

    // local_feats = g @ w_gcn2^T
    gemm(gg, wbf + W_GCN2, lf, 32768, 512, 512, 0, 0, 0, 1);

    // glob = relu(fuse over bins + b_fuse)
    fuse_glob<<<2048, 256>>>((const __nv_bfloat162*)lf, w_fuse, b_fuse,
                             (__nv_bfloat162*)glob);

    // query / key / value^T
    gemm(xp, wbf + W_Q, qry, 65536, 256, 512, 0, 0, 0, 1, 1, b_q, 2);
    gemm(lf, wbf + W_K, key, 32768, 256, 512, 0, 0, 0, 1, 1, b_k, 2);
    gemm(wbf + W_V, glob, valT, 256, 512, 512, 0, 262144, 131072, 4, 1, b_v, 1);

    // aff = query @ key^T per (b,bin); softmax over k
    gemm(qry, key, aff, 1024, 512, 256, 262144, 131072, 524288, 64);
    softmax_rows<false><<<65536, 64>>>(aff, nullptr, 512);

    // out_attn = aff @ value (value shared across bins: zdivB=16)
    gemm(aff, valT, oat, 1024, 256, 512, 524288, 131072, 262144, 64, 16);

    // final 1x1 conv + BN + relu + residual, patch-recover fused epilogue
    gemm(wbf + W_OUT, oat, nullptr, 512, 1024, 256, 0, 262144, 0, 64, 1,
         nullptr, 0, nullptr, 0, 2, x, bnS, bnT, out);
}